// round 6
// baseline (speedup 1.0000x reference)
#include <cuda_runtime.h>
#include <math.h>
#include <stdint.h>

// Problem constants
#define Bz 64
#define Tt 512
#define Dd 1024
#define Hh 1024
#define G4 4096   // 4*H

// ---------------------------------------------------------------------------
// Scratch (static __device__ globals; no allocation allowed)
// ---------------------------------------------------------------------------
__device__ float g_xz[(size_t)Tt * Bz * G4];   // 512 MB  (time-major: [t][b][4H])
__device__ float g_hs0[(size_t)Tt * Bz * Hh];  // 128 MB  (layer0 hs, time-major [t][b][H])
__device__ float g_h[2][Bz * Hh];              // ping-pong h
__device__ float g_c[Bz * Hh];                 // cell state

// software grid barrier state (returns to 0 after each launch: even #flips)
__device__ unsigned g_bar_count = 0;
__device__ unsigned g_bar_sense = 0;

// ---------------------------------------------------------------------------
// Grid-wide sync for a fully-resident grid (sense-reversing barrier).
// ---------------------------------------------------------------------------
__device__ __forceinline__ void grid_sync(unsigned& sense, unsigned nblocks) {
    __threadfence();
    __syncthreads();
    if (threadIdx.x == 0) {
        const unsigned s = sense ^ 1u;
        sense = s;
        if (atomicAdd(&g_bar_count, 1u) == nblocks - 1u) {
            atomicExch(&g_bar_count, 0u);
            __threadfence();
            atomicExch(&g_bar_sense, s);
        } else {
            while (atomicAdd(&g_bar_sense, 0u) != s) { __nanosleep(64); }
        }
    }
    __syncthreads();
}

// ---------------------------------------------------------------------------
// tf32 helpers
// ---------------------------------------------------------------------------
__device__ __forceinline__ void split_tf32(float x, uint32_t& hi, uint32_t& lo) {
    uint32_t h;
    asm("cvt.rna.tf32.f32 %0, %1;" : "=r"(h) : "f"(x));
    const float hf = __uint_as_float(h);
    const float lf = x - hf;
    uint32_t l;
    asm("cvt.rna.tf32.f32 %0, %1;" : "=r"(l) : "f"(lf));
    hi = h; lo = l;
}

__device__ __forceinline__ void mma_tf32(float* c, const uint32_t* a, const uint32_t* b) {
    asm volatile(
        "mma.sync.aligned.m16n8k8.row.col.f32.tf32.tf32.f32 "
        "{%0,%1,%2,%3}, {%4,%5,%6,%7}, {%8,%9}, {%0,%1,%2,%3};"
        : "+f"(c[0]), "+f"(c[1]), "+f"(c[2]), "+f"(c[3])
        : "r"(a[0]), "r"(a[1]), "r"(a[2]), "r"(a[3]), "r"(b[0]), "r"(b[1]));
}

// ---------------------------------------------------------------------------
// Tensor-core GEMM (3xTF32 split): xz = A @ W + bias
// A is (32768 x 1024): layer0 A[m][k] = x[b][t][k] with m = t*B + b (x is B,T,D)
//                      layer1 A[m][k] = g_hs0[m][k]
// W (1024 x 4096) row-major.  C tile 128x128 per block, BK=16, 256 threads.
// 8 warps: warp tile 64x32 (wm = wid>>2, wn = wid&3).
// Fragments loaded straight from smem (padded stride 136 -> conflict-light).
// ---------------------------------------------------------------------------
#define SMP 136   // padded row stride (mod 32 banks = 8 -> a/b frag loads conflict-free)

__global__ void __launch_bounds__(256) gemm_xz_kernel(
    const float* __restrict__ Aext, const float* __restrict__ W,
    const float* __restrict__ bias, int layer0)
{
    __shared__ uint32_t As_hi[16][SMP];
    __shared__ uint32_t As_lo[16][SMP];
    __shared__ uint32_t Bs_hi[16][SMP];
    __shared__ uint32_t Bs_lo[16][SMP];

    const int tid = threadIdx.x;
    const int bm = blockIdx.y * 128;
    const int bn = blockIdx.x * 128;

    const int wid = tid >> 5;
    const int lane = tid & 31;
    const int wm = wid >> 2;        // 0..1  -> m offset 64*wm
    const int wn = wid & 3;         // 0..3  -> n offset 32*wn
    const int gid = lane >> 2;      // 0..7
    const int tig = lane & 3;       // 0..3

    // GMEM A load mapping: 128 rows x 16 k, 8 floats per thread
    const int aRow = tid >> 1;              // 0..127
    const int aCol = (tid & 1) << 3;        // 0 or 8
    const float* aptr;
    {
        const int m = bm + aRow;
        if (layer0) {
            aptr = Aext + ((size_t)(m & 63) * Tt + (m >> 6)) * Dd;
        } else {
            aptr = g_hs0 + (size_t)m * Hh;
        }
    }
    // GMEM B load mapping: 16 rows x 128 n, 8 floats per thread
    const int bRow = tid >> 4;              // 0..15
    const int bCol = (tid & 15) << 3;       // 0..120
    const float* wptr = W + (size_t)bRow * G4 + bn + bCol;

    // preload k-block 0
    float4 ra0 = *(const float4*)(aptr + aCol);
    float4 ra1 = *(const float4*)(aptr + aCol + 4);
    float4 rb0 = *(const float4*)(wptr);
    float4 rb1 = *(const float4*)(wptr + 4);

    // accumulators: [m-tile][n-tile][4]
    float acc[4][4][4];
#pragma unroll
    for (int i = 0; i < 4; i++)
#pragma unroll
        for (int j = 0; j < 4; j++)
#pragma unroll
            for (int q = 0; q < 4; q++) acc[i][j][q] = 0.0f;

    // store k-block 0 to smem (split)
    {
        const float av[8] = {ra0.x, ra0.y, ra0.z, ra0.w, ra1.x, ra1.y, ra1.z, ra1.w};
        const float bv[8] = {rb0.x, rb0.y, rb0.z, rb0.w, rb1.x, rb1.y, rb1.z, rb1.w};
#pragma unroll
        for (int j = 0; j < 8; j++) {
            uint32_t h, l;
            split_tf32(av[j], h, l);
            As_hi[aCol + j][aRow] = h; As_lo[aCol + j][aRow] = l;
            split_tf32(bv[j], h, l);
            Bs_hi[bRow][bCol + j] = h; Bs_lo[bRow][bCol + j] = l;
        }
    }
    __syncthreads();

    for (int k0 = 0; k0 < 1024; k0 += 16) {
        const bool more = (k0 + 16 < 1024);
        if (more) {
            ra0 = *(const float4*)(aptr + k0 + 16 + aCol);
            ra1 = *(const float4*)(aptr + k0 + 16 + aCol + 4);
            rb0 = *(const float4*)(wptr + (size_t)(k0 + 16) * G4);
            rb1 = *(const float4*)(wptr + (size_t)(k0 + 16) * G4 + 4);
        }

        // two k8 steps
#pragma unroll
        for (int s = 0; s < 2; s++) {
            const int ks = s * 8;
            uint32_t a_hi[4][4], a_lo[4][4], b_hi[4][2], b_lo[4][2];
#pragma unroll
            for (int mt = 0; mt < 4; mt++) {
                const int m = wm * 64 + mt * 16 + gid;
                a_hi[mt][0] = As_hi[ks + tig][m];
                a_hi[mt][1] = As_hi[ks + tig][m + 8];
                a_hi[mt][2] = As_hi[ks + tig + 4][m];
                a_hi[mt][3] = As_hi[ks + tig + 4][m + 8];
                a_lo[mt][0] = As_lo[ks + tig][m];
                a_lo[mt][1] = As_lo[ks + tig][m + 8];
                a_lo[mt][2] = As_lo[ks + tig + 4][m];
                a_lo[mt][3] = As_lo[ks + tig + 4][m + 8];
            }
#pragma unroll
            for (int nt = 0; nt < 4; nt++) {
                const int n = wn * 32 + nt * 8 + gid;
                b_hi[nt][0] = Bs_hi[ks + tig][n];
                b_hi[nt][1] = Bs_hi[ks + tig + 4][n];
                b_lo[nt][0] = Bs_lo[ks + tig][n];
                b_lo[nt][1] = Bs_lo[ks + tig + 4][n];
            }
#pragma unroll
            for (int mt = 0; mt < 4; mt++)
#pragma unroll
                for (int nt = 0; nt < 4; nt++) {
                    mma_tf32(acc[mt][nt], a_hi[mt], b_hi[nt]);
                    mma_tf32(acc[mt][nt], a_hi[mt], b_lo[nt]);
                    mma_tf32(acc[mt][nt], a_lo[mt], b_hi[nt]);
                }
        }
        __syncthreads();
        if (more) {
            const float av[8] = {ra0.x, ra0.y, ra0.z, ra0.w, ra1.x, ra1.y, ra1.z, ra1.w};
            const float bv[8] = {rb0.x, rb0.y, rb0.z, rb0.w, rb1.x, rb1.y, rb1.z, rb1.w};
#pragma unroll
            for (int j = 0; j < 8; j++) {
                uint32_t h, l;
                split_tf32(av[j], h, l);
                As_hi[aCol + j][aRow] = h; As_lo[aCol + j][aRow] = l;
                split_tf32(bv[j], h, l);
                Bs_hi[bRow][bCol + j] = h; Bs_lo[bRow][bCol + j] = l;
            }
            __syncthreads();
        }
    }

    // epilogue: + bias, store to g_xz
#pragma unroll
    for (int mt = 0; mt < 4; mt++) {
#pragma unroll
        for (int nt = 0; nt < 4; nt++) {
            const int gn = bn + wn * 32 + nt * 8 + 2 * tig;
            const float b0v = bias[gn];
            const float b1v = bias[gn + 1];
            const int r0 = bm + wm * 64 + mt * 16 + gid;
            float* p0 = g_xz + (size_t)r0 * G4 + gn;
            float* p1 = g_xz + (size_t)(r0 + 8) * G4 + gn;
            p0[0] = acc[mt][nt][0] + b0v;
            p0[1] = acc[mt][nt][1] + b1v;
            p1[0] = acc[mt][nt][2] + b0v;
            p1[1] = acc[mt][nt][3] + b1v;
        }
    }
}

// ---------------------------------------------------------------------------
// Persistent LSTM scan: ONE kernel does all 512 timesteps for one layer.
// grid = 128 blocks (8 hidden-cols each -> 32 gate-cols), 128 threads.
// (unchanged from round 5 — proven correct; next optimization target)
// ---------------------------------------------------------------------------
__global__ void __launch_bounds__(128) lstm_scan_kernel(
    const float* __restrict__ U, const int* __restrict__ lengths,
    float* __restrict__ out_base, int layer)
{
    __shared__ float hsm[32][64];   // [k][b]
    __shared__ float usm[32][36];   // [k][c]  (padded)
    __shared__ float zsm[64][32];   // [b][c]

    const int tid = threadIdx.x;
    const int j0 = blockIdx.x * 8;
    const unsigned nblocks = gridDim.x;
    unsigned sense = 0;

    // zero h (both buffers) and c, distributed over the whole grid
    {
        const int base = blockIdx.x * 128 + tid;   // 0..16383
#pragma unroll
        for (int q = 0; q < 4; q++) {
            const int i = base + q * 16384;
            g_h[0][i] = 0.0f;
            g_h[1][i] = 0.0f;
            g_c[i] = 0.0f;
        }
    }
    grid_sync(sense, nblocks);   // sync #1

    const int tr = tid >> 3;     // 0..15 (rows 4tr..4tr+3)
    const int tc = tid & 7;      // 0..7  (cols 4tc..4tc+3)
    const int hb = tid >> 1;            // 0..63
    const int hkq = (tid & 1) << 4;     // 0 or 16
    const int uk = tid >> 2;            // 0..31
    const int ug = tid & 3;             // groups ug, ug+4

    int len_b[4];
#pragma unroll
    for (int r = 0; r < 4; r++) {
        const int p = r * 128 + tid;
        len_b[r] = lengths[p >> 3];
    }

    for (int t = 0; t < Tt; t++) {
        const float* __restrict__ hin = g_h[t & 1];
        float* __restrict__ hout = g_h[(t & 1) ^ 1];
        const float* __restrict__ xz = g_xz + (size_t)t * (Bz * G4);

        float acc[4][4];
#pragma unroll
        for (int i = 0; i < 4; i++)
#pragma unroll
            for (int j = 0; j < 4; j++) acc[i][j] = 0.0f;

        for (int k0 = 0; k0 < Hh; k0 += 32) {
#pragma unroll
            for (int q = 0; q < 4; q++) {
                float4 v = __ldcg((const float4*)(hin + (size_t)hb * Hh + k0 + hkq + q * 4));
                hsm[hkq + q * 4 + 0][hb] = v.x;
                hsm[hkq + q * 4 + 1][hb] = v.y;
                hsm[hkq + q * 4 + 2][hb] = v.z;
                hsm[hkq + q * 4 + 3][hb] = v.w;
            }
#pragma unroll
            for (int q = 0; q < 2; q++) {
                const int g = ug + q * 4;           // 0..7
                const int gate = g >> 1;
                const int cj = (g & 1) * 4;
                const float* up = U + (size_t)(k0 + uk) * G4 + gate * Hh + j0 + cj;
                *(float4*)&usm[uk][g * 4] = *(const float4*)up;
            }
            __syncthreads();
#pragma unroll
            for (int k = 0; k < 32; k++) {
                float4 hv = *(const float4*)&hsm[k][tr * 4];
                float4 uv = *(const float4*)&usm[k][tc * 4];
                float hvv[4] = {hv.x, hv.y, hv.z, hv.w};
                float uvv[4] = {uv.x, uv.y, uv.z, uv.w};
#pragma unroll
                for (int i = 0; i < 4; i++)
#pragma unroll
                    for (int j = 0; j < 4; j++) acc[i][j] += hvv[i] * uvv[j];
            }
            __syncthreads();
        }

#pragma unroll
        for (int i = 0; i < 4; i++) {
            const int b = tr * 4 + i;
#pragma unroll
            for (int j = 0; j < 4; j++) {
                const int cc = tc * 4 + j;
                const int gate = cc >> 3;
                const int jj = cc & 7;
                zsm[b][cc] = acc[i][j] + xz[(size_t)b * G4 + gate * Hh + j0 + jj];
            }
        }
        __syncthreads();

#pragma unroll
        for (int r = 0; r < 4; r++) {
            const int p = r * 128 + tid;
            const int b = p >> 3;
            const int jj = p & 7;
            const int j = j0 + jj;

            const float zi = zsm[b][jj];
            const float zf = zsm[b][8 + jj];
            const float zg = zsm[b][16 + jj];
            const float zo = zsm[b][24 + jj];

            const float ig = 1.0f / (1.0f + __expf(-zi));
            const float fg = 1.0f / (1.0f + __expf(-zf));
            const float gg = tanhf(zg);
            const float og = 1.0f / (1.0f + __expf(-zo));

            const size_t hidx = (size_t)b * Hh + j;
            const float cold = g_c[hidx];
            const float cn = fg * cold + ig * gg;
            const float hn = og * tanhf(cn);

            const bool msk = (t < len_b[r]);
            const float h2 = msk ? hn : __ldcg(hin + hidx);
            const float c2 = msk ? cn : cold;

            __stcg(hout + hidx, h2);
            g_c[hidx] = c2;
            if (layer == 0) {
                g_hs0[(size_t)t * (Bz * Hh) + hidx] = h2;
            } else {
                out_base[(size_t)b * ((size_t)Tt * Hh) + (size_t)t * Hh + j] = h2;
            }
        }

        if (t < Tt - 1) grid_sync(sense, nblocks);
    }
}

// ---------------------------------------------------------------------------
// Copy final h, c into output tail
// ---------------------------------------------------------------------------
__global__ void copy_hc_kernel(float* __restrict__ out_tail) {
    int i = blockIdx.x * 256 + threadIdx.x;
    if (i < Bz * Hh) {
        out_tail[i] = g_h[0][i];              // T=512 even -> final h in buf 0
        out_tail[Bz * Hh + i] = g_c[i];
    }
}

// ---------------------------------------------------------------------------
// Launch: 5 graph nodes
// ---------------------------------------------------------------------------
extern "C" void kernel_launch(void* const* d_in, const int* in_sizes, int n_in,
                              void* d_out, int out_size) {
    (void)in_sizes; (void)n_in; (void)out_size;
    const float* x  = (const float*)d_in[0];
    const int* lens = (const int*)d_in[1];
    const float* W0 = (const float*)d_in[2];
    const float* U0 = (const float*)d_in[3];
    const float* b0 = (const float*)d_in[4];
    const float* W1 = (const float*)d_in[5];
    const float* U1 = (const float*)d_in[6];
    const float* b1 = (const float*)d_in[7];
    float* out = (float*)d_out;

    const dim3 ggrid(G4 / 128, (Tt * Bz) / 128);   // 32 x 256
    const int hcBlocks = (Bz * Hh + 255) / 256;

    // Layer 0
    gemm_xz_kernel<<<ggrid, 256>>>(x, W0, b0, 1);
    lstm_scan_kernel<<<128, 128>>>(U0, lens, nullptr, 0);

    // Layer 1
    gemm_xz_kernel<<<ggrid, 256>>>(nullptr, W1, b1, 0);
    lstm_scan_kernel<<<128, 128>>>(U1, lens, out, 1);

    // Final h, c
    copy_hc_kernel<<<hcBlocks, 256>>>(out + (size_t)Bz * Tt * Hh);
}

// round 7
// speedup vs baseline: 1.1373x; 1.1373x over previous
#include <cuda_runtime.h>
#include <math.h>
#include <stdint.h>

// Problem constants
#define Bz 64
#define Tt 512
#define Dd 1024
#define Hh 1024
#define G4 4096   // 4*H

// ---------------------------------------------------------------------------
// Scratch (static __device__ globals; no allocation allowed)
// ---------------------------------------------------------------------------
__device__ float g_xz[(size_t)Tt * Bz * G4];   // 512 MB (time-major: [t][b][4H])
__device__ float g_hs0[(size_t)Tt * Bz * Hh];  // 128 MB (layer0 hs, [t][b][H])
__device__ float g_hT[2][Hh][Bz];              // transposed h ping-pong [k][b]
__device__ float4 g_Upk[16 * 128 * 8 * 32 * 4]; // 33.5 MB packed/split U

// software grid barrier state (returns to 0 after each launch: even #flips)
__device__ unsigned g_bar_count = 0;
__device__ unsigned g_bar_sense = 0;

__device__ __forceinline__ void grid_sync(unsigned& sense, unsigned nblocks) {
    __threadfence();
    __syncthreads();
    if (threadIdx.x == 0) {
        const unsigned s = sense ^ 1u;
        sense = s;
        if (atomicAdd(&g_bar_count, 1u) == nblocks - 1u) {
            atomicExch(&g_bar_count, 0u);
            __threadfence();
            atomicExch(&g_bar_sense, s);
        } else {
            while (atomicAdd(&g_bar_sense, 0u) != s) { __nanosleep(64); }
        }
    }
    __syncthreads();
}

// ---------------------------------------------------------------------------
// tf32 helpers
// ---------------------------------------------------------------------------
__device__ __forceinline__ void split_tf32(float x, uint32_t& hi, uint32_t& lo) {
    uint32_t h;
    asm("cvt.rna.tf32.f32 %0, %1;" : "=r"(h) : "f"(x));
    const float hf = __uint_as_float(h);
    const float lf = x - hf;
    uint32_t l;
    asm("cvt.rna.tf32.f32 %0, %1;" : "=r"(l) : "f"(lf));
    hi = h; lo = l;
}

__device__ __forceinline__ void mma_tf32(float* c, const uint32_t* a, const uint32_t* b) {
    asm volatile(
        "mma.sync.aligned.m16n8k8.row.col.f32.tf32.tf32.f32 "
        "{%0,%1,%2,%3}, {%4,%5,%6,%7}, {%8,%9}, {%0,%1,%2,%3};"
        : "+f"(c[0]), "+f"(c[1]), "+f"(c[2]), "+f"(c[3])
        : "r"(a[0]), "r"(a[1]), "r"(a[2]), "r"(a[3]), "r"(b[0]), "r"(b[1]));
}

__device__ __forceinline__ void cp16(void* dst_smem, const void* src) {
    uint32_t d = (uint32_t)__cvta_generic_to_shared(dst_smem);
    asm volatile("cp.async.cg.shared.global [%0], [%1], 16;" :: "r"(d), "l"(src));
}
#define CP_COMMIT() asm volatile("cp.async.commit_group;")
#define CP_WAIT0()  asm volatile("cp.async.wait_group 0;")

// ---------------------------------------------------------------------------
// Tensor-core GEMM (3xTF32 split): xz = A @ W + bias   (unchanged from R6)
// ---------------------------------------------------------------------------
#define SMP 136

__global__ void __launch_bounds__(256) gemm_xz_kernel(
    const float* __restrict__ Aext, const float* __restrict__ W,
    const float* __restrict__ bias, int layer0)
{
    __shared__ uint32_t As_hi[16][SMP];
    __shared__ uint32_t As_lo[16][SMP];
    __shared__ uint32_t Bs_hi[16][SMP];
    __shared__ uint32_t Bs_lo[16][SMP];

    const int tid = threadIdx.x;
    const int bm = blockIdx.y * 128;
    const int bn = blockIdx.x * 128;

    const int wid = tid >> 5;
    const int lane = tid & 31;
    const int wm = wid >> 2;
    const int wn = wid & 3;
    const int gid = lane >> 2;
    const int tig = lane & 3;

    const int aRow = tid >> 1;
    const int aCol = (tid & 1) << 3;
    const float* aptr;
    {
        const int m = bm + aRow;
        if (layer0) aptr = Aext + ((size_t)(m & 63) * Tt + (m >> 6)) * Dd;
        else        aptr = g_hs0 + (size_t)m * Hh;
    }
    const int bRow = tid >> 4;
    const int bCol = (tid & 15) << 3;
    const float* wptr = W + (size_t)bRow * G4 + bn + bCol;

    float4 ra0 = *(const float4*)(aptr + aCol);
    float4 ra1 = *(const float4*)(aptr + aCol + 4);
    float4 rb0 = *(const float4*)(wptr);
    float4 rb1 = *(const float4*)(wptr + 4);

    float acc[4][4][4];
#pragma unroll
    for (int i = 0; i < 4; i++)
#pragma unroll
        for (int j = 0; j < 4; j++)
#pragma unroll
            for (int q = 0; q < 4; q++) acc[i][j][q] = 0.0f;

    {
        const float av[8] = {ra0.x, ra0.y, ra0.z, ra0.w, ra1.x, ra1.y, ra1.z, ra1.w};
        const float bv[8] = {rb0.x, rb0.y, rb0.z, rb0.w, rb1.x, rb1.y, rb1.z, rb1.w};
#pragma unroll
        for (int j = 0; j < 8; j++) {
            uint32_t h, l;
            split_tf32(av[j], h, l);
            As_hi[aCol + j][aRow] = h; As_lo[aCol + j][aRow] = l;
            split_tf32(bv[j], h, l);
            Bs_hi[bRow][bCol + j] = h; Bs_lo[bRow][bCol + j] = l;
        }
    }
    __syncthreads();

    for (int k0 = 0; k0 < 1024; k0 += 16) {
        const bool more = (k0 + 16 < 1024);
        if (more) {
            ra0 = *(const float4*)(aptr + k0 + 16 + aCol);
            ra1 = *(const float4*)(aptr + k0 + 16 + aCol + 4);
            rb0 = *(const float4*)(wptr + (size_t)(k0 + 16) * G4);
            rb1 = *(const float4*)(wptr + (size_t)(k0 + 16) * G4 + 4);
        }
#pragma unroll
        for (int s = 0; s < 2; s++) {
            const int ks = s * 8;
            uint32_t a_hi[4][4], a_lo[4][4], b_hi[4][2], b_lo[4][2];
#pragma unroll
            for (int mt = 0; mt < 4; mt++) {
                const int m = wm * 64 + mt * 16 + gid;
                a_hi[mt][0] = As_hi[ks + tig][m];
                a_hi[mt][1] = As_hi[ks + tig][m + 8];
                a_hi[mt][2] = As_hi[ks + tig + 4][m];
                a_hi[mt][3] = As_hi[ks + tig + 4][m + 8];
                a_lo[mt][0] = As_lo[ks + tig][m];
                a_lo[mt][1] = As_lo[ks + tig][m + 8];
                a_lo[mt][2] = As_lo[ks + tig + 4][m];
                a_lo[mt][3] = As_lo[ks + tig + 4][m + 8];
            }
#pragma unroll
            for (int nt = 0; nt < 4; nt++) {
                const int n = wn * 32 + nt * 8 + gid;
                b_hi[nt][0] = Bs_hi[ks + tig][n];
                b_hi[nt][1] = Bs_hi[ks + tig + 4][n];
                b_lo[nt][0] = Bs_lo[ks + tig][n];
                b_lo[nt][1] = Bs_lo[ks + tig + 4][n];
            }
#pragma unroll
            for (int mt = 0; mt < 4; mt++)
#pragma unroll
                for (int nt = 0; nt < 4; nt++) {
                    mma_tf32(acc[mt][nt], a_hi[mt], b_hi[nt]);
                    mma_tf32(acc[mt][nt], a_hi[mt], b_lo[nt]);
                    mma_tf32(acc[mt][nt], a_lo[mt], b_hi[nt]);
                }
        }
        __syncthreads();
        if (more) {
            const float av[8] = {ra0.x, ra0.y, ra0.z, ra0.w, ra1.x, ra1.y, ra1.z, ra1.w};
            const float bv[8] = {rb0.x, rb0.y, rb0.z, rb0.w, rb1.x, rb1.y, rb1.z, rb1.w};
#pragma unroll
            for (int j = 0; j < 8; j++) {
                uint32_t h, l;
                split_tf32(av[j], h, l);
                As_hi[aCol + j][aRow] = h; As_lo[aCol + j][aRow] = l;
                split_tf32(bv[j], h, l);
                Bs_hi[bRow][bCol + j] = h; Bs_lo[bRow][bCol + j] = l;
            }
            __syncthreads();
        }
    }

#pragma unroll
    for (int mt = 0; mt < 4; mt++) {
#pragma unroll
        for (int nt = 0; nt < 4; nt++) {
            const int gn = bn + wn * 32 + nt * 8 + 2 * tig;
            const float b0v = bias[gn];
            const float b1v = bias[gn + 1];
            const int r0 = bm + wm * 64 + mt * 16 + gid;
            float* p0 = g_xz + (size_t)r0 * G4 + gn;
            float* p1 = g_xz + (size_t)(r0 + 8) * G4 + gn;
            p0[0] = acc[mt][nt][0] + b0v;
            p0[1] = acc[mt][nt][1] + b1v;
            p1[0] = acc[mt][nt][2] + b0v;
            p1[1] = acc[mt][nt][3] + b1v;
        }
    }
}

// ---------------------------------------------------------------------------
// U prep: split to tf32 hi/lo and pack in fragment order.
// Layout: [chunk c (16)][block (128)][k8 (8)][n (32)][tig (4)] as float4
//         float4 = ( hi(k=kt), lo(kt), hi(kt+4), lo(kt+4) ), kt = c*64+k8*8+tig
//         n within block: gate = n>>3, jj = n&7 -> U col = gate*1024 + blk*8 + jj
// ---------------------------------------------------------------------------
__global__ void __launch_bounds__(256) prep_upk_kernel(const float* __restrict__ U) {
    const int i = blockIdx.x * 256 + threadIdx.x;   // 0 .. 2097151
    const int tig = i & 3;
    const int n   = (i >> 2) & 31;
    const int k8  = (i >> 7) & 7;
    const int blk = (i >> 10) & 127;
    const int c   = i >> 17;
    const int kt = c * 64 + k8 * 8 + tig;
    const int gate = n >> 3, jj = n & 7;
    const int gcol = gate * Hh + blk * 8 + jj;
    const float u1 = U[(size_t)kt * G4 + gcol];
    const float u2 = U[(size_t)(kt + 4) * G4 + gcol];
    uint32_t h1, l1, h2, l2;
    split_tf32(u1, h1, l1);
    split_tf32(u2, h2, l2);
    g_Upk[i] = make_float4(__uint_as_float(h1), __uint_as_float(l1),
                           __uint_as_float(h2), __uint_as_float(l2));
}

// ---------------------------------------------------------------------------
// Persistent tensor-core LSTM scan.
// 128 blocks x 128 threads (4 warps). Block: 64 batch x 32 gate-cols
// (hidden cols j0..j0+7, all 4 gates). Warp wid: rows 16*wid..16*wid+15,
// warp tile 16x32 via 4 n-tiles of m16n8k8, 3-pass tf32 split.
// nt == gate, so each thread's acc holds all 4 gates of its (b,j) cells:
// c-state and prev-h live in registers for all 512 steps.
// ---------------------------------------------------------------------------
#define HB_STRIDE 72
#define HBUF_FLOATS (64 * HB_STRIDE)           // per stage
#define SCAN_SMEM (2 * HBUF_FLOATS * 4 + 2 * 1024 * 16)   // 36864 + 32768 B

__device__ __forceinline__ void copy_chunk(
    float* hbuf, float4* ubuf, int c, int s, int par, int tid, int blk)
{
    // h chunk: 64 k-rows x 64 b, fp32; row = 256B contiguous in g_hT
    const int kk = tid >> 1;
    const int boff = (tid & 1) * 32;
    const float* hsrc = &g_hT[par][c * 64 + kk][boff];
    float* hdst = hbuf + s * HBUF_FLOATS + kk * HB_STRIDE + boff;
#pragma unroll
    for (int q = 0; q < 8; q++) cp16(hdst + q * 4, hsrc + q * 4);
    // U chunk: contiguous 16KB blob
    const float4* usrc = g_Upk + ((size_t)c * 128 + blk) * 1024 + tid * 8;
    float4* udst = ubuf + s * 1024 + tid * 8;
#pragma unroll
    for (int q = 0; q < 8; q++) cp16(udst + q, usrc + q);
}

__global__ void __launch_bounds__(128, 1) lstm_scan_tc(
    const int* __restrict__ lengths, float* __restrict__ out_base,
    float* __restrict__ out_tail, int layer)
{
    extern __shared__ float sm[];
    float* hbuf = sm;
    float4* ubuf = (float4*)(sm + 2 * HBUF_FLOATS);

    const int tid = threadIdx.x;
    const int blk = blockIdx.x;
    const int wid = tid >> 5;
    const int lane = tid & 31;
    const int gid = lane >> 2;
    const int tig = lane & 3;
    const int m0 = wid * 16;
    const int j0 = blk * 8;
    unsigned sense = 0;

    // zero g_hT[0] (initial h state)
    {
        const int base = (blk * 128 + tid) * 4;   // covers 65536 floats
        *(float4*)&(((float*)g_hT)[base]) = make_float4(0.f, 0.f, 0.f, 0.f);
    }

    const int b0 = m0 + gid;
    const int b1 = b0 + 8;
    const int jA = j0 + 2 * tig;
    const int len0 = lengths[b0];
    const int len1 = lengths[b1];

    float cb[4] = {0.f, 0.f, 0.f, 0.f};   // cell state (regs, persistent)
    float hp[4] = {0.f, 0.f, 0.f, 0.f};   // prev h (regs)

    grid_sync(sense, gridDim.x);   // sync #1 (h0 zeros visible)

    for (int t = 0; t < Tt; t++) {
        // xz prefetch (independent of h -> issue before the barrier)
        const float* xz = g_xz + (size_t)t * (Bz * G4);
        float2 xv[4][2];
#pragma unroll
        for (int g = 0; g < 4; g++) {
            xv[g][0] = *(const float2*)(xz + (size_t)b0 * G4 + g * Hh + jA);
            xv[g][1] = *(const float2*)(xz + (size_t)b1 * G4 + g * Hh + jA);
        }
        if (t) grid_sync(sense, gridDim.x);
        const int par = t & 1;

        float acc[4][4];
#pragma unroll
        for (int nt = 0; nt < 4; nt++)
#pragma unroll
            for (int q = 0; q < 4; q++) acc[nt][q] = 0.0f;

        // k loop: 16 chunks of K=64, cp.async double-buffered
        copy_chunk(hbuf, ubuf, 0, 0, par, tid, blk);
        CP_COMMIT();
        int s = 0;
        for (int c = 0; c < 16; c++) {
            CP_WAIT0();
            __syncthreads();
            if (c < 15) { copy_chunk(hbuf, ubuf, c + 1, s ^ 1, par, tid, blk); CP_COMMIT(); }

            const float* hb = hbuf + s * HBUF_FLOATS;
            const float4* ub = ubuf + s * 1024;
#pragma unroll
            for (int k8 = 0; k8 < 8; k8++) {
                const float a0 = hb[(k8 * 8 + tig) * HB_STRIDE + b0];
                const float a1 = hb[(k8 * 8 + tig) * HB_STRIDE + b0 + 8];
                const float a2 = hb[(k8 * 8 + tig + 4) * HB_STRIDE + b0];
                const float a3 = hb[(k8 * 8 + tig + 4) * HB_STRIDE + b0 + 8];
                uint32_t ah[4], al[4];
                split_tf32(a0, ah[0], al[0]);
                split_tf32(a1, ah[1], al[1]);
                split_tf32(a2, ah[2], al[2]);
                split_tf32(a3, ah[3], al[3]);
#pragma unroll
                for (int nt = 0; nt < 4; nt++) {
                    const float4 bv = ub[(k8 * 32 + nt * 8 + gid) * 4 + tig];
                    uint32_t bh[2], bl[2];
                    bh[0] = __float_as_uint(bv.x); bh[1] = __float_as_uint(bv.z);
                    bl[0] = __float_as_uint(bv.y); bl[1] = __float_as_uint(bv.w);
                    mma_tf32(acc[nt], ah, bh);
                    mma_tf32(acc[nt], ah, bl);
                    mma_tf32(acc[nt], al, bh);
                }
            }
            s ^= 1;
        }

        // epilogue: gates + state update, all in registers
#pragma unroll
        for (int q = 0; q < 4; q++) {
            const int r = q >> 1;        // 0: row b0, 1: row b1
            const int ccsel = q & 1;     // 0: jA, 1: jA+1
            const float xi = ccsel ? xv[0][r].y : xv[0][r].x;
            const float xf = ccsel ? xv[1][r].y : xv[1][r].x;
            const float xg = ccsel ? xv[2][r].y : xv[2][r].x;
            const float xo = ccsel ? xv[3][r].y : xv[3][r].x;

            const float zi = acc[0][q] + xi;
            const float zf = acc[1][q] + xf;
            const float zg = acc[2][q] + xg;
            const float zo = acc[3][q] + xo;

            const float ig = 1.0f / (1.0f + __expf(-zi));
            const float fg = 1.0f / (1.0f + __expf(-zf));
            const float gg = tanhf(zg);
            const float og = 1.0f / (1.0f + __expf(-zo));

            const float cn = fg * cb[q] + ig * gg;
            const float hn = og * tanhf(cn);

            const bool msk = t < (r ? len1 : len0);
            const float h2 = msk ? hn : hp[q];
            const float c2 = msk ? cn : cb[q];
            hp[q] = h2; cb[q] = c2;

            const int b = r ? b1 : b0;
            const int j = jA + ccsel;
            __stcg(&g_hT[par ^ 1][j][b], h2);
            if (layer == 0) {
                g_hs0[(size_t)t * (Bz * Hh) + (size_t)b * Hh + j] = h2;
            } else {
                out_base[(size_t)b * ((size_t)Tt * Hh) + (size_t)t * Hh + j] = h2;
            }
        }
        // total grid_syncs per launch: 512 (even) -> barrier state returns to 0
    }

    // final h, c (post-mask register state)
    if (layer) {
#pragma unroll
        for (int q = 0; q < 4; q++) {
            const int b = (q >> 1) ? b1 : b0;
            const int j = jA + (q & 1);
            out_tail[(size_t)b * Hh + j] = hp[q];
            out_tail[(size_t)Bz * Hh + (size_t)b * Hh + j] = cb[q];
        }
    }
}

// ---------------------------------------------------------------------------
// Launch: 7 graph nodes
// ---------------------------------------------------------------------------
extern "C" void kernel_launch(void* const* d_in, const int* in_sizes, int n_in,
                              void* d_out, int out_size) {
    (void)in_sizes; (void)n_in; (void)out_size;
    const float* x  = (const float*)d_in[0];
    const int* lens = (const int*)d_in[1];
    const float* W0 = (const float*)d_in[2];
    const float* U0 = (const float*)d_in[3];
    const float* b0 = (const float*)d_in[4];
    const float* W1 = (const float*)d_in[5];
    const float* U1 = (const float*)d_in[6];
    const float* b1 = (const float*)d_in[7];
    float* out = (float*)d_out;

    cudaFuncSetAttribute(lstm_scan_tc,
                         cudaFuncAttributeMaxDynamicSharedMemorySize, SCAN_SMEM);

    const dim3 ggrid(G4 / 128, (Tt * Bz) / 128);   // 32 x 256

    // Layer 0
    gemm_xz_kernel<<<ggrid, 256>>>(x, W0, b0, 1);
    prep_upk_kernel<<<8192, 256>>>(U0);
    lstm_scan_tc<<<128, 128, SCAN_SMEM>>>(lens, nullptr, nullptr, 0);

    // Layer 1
    gemm_xz_kernel<<<ggrid, 256>>>(nullptr, W1, b1, 0);
    prep_upk_kernel<<<8192, 256>>>(U1);
    float* tail = out + (size_t)Bz * Tt * Hh;
    lstm_scan_tc<<<128, 128, SCAN_SMEM>>>(lens, out, tail, 1);
}

// round 8
// speedup vs baseline: 1.2444x; 1.0942x over previous
#include <cuda_runtime.h>
#include <math.h>
#include <stdint.h>

// Problem constants
#define Bz 64
#define Tt 512
#define Dd 1024
#define Hh 1024
#define G4 4096   // 4*H

// ---------------------------------------------------------------------------
// Scratch (static __device__ globals; no allocation allowed)
// ---------------------------------------------------------------------------
__device__ float g_xz[(size_t)Tt * Bz * G4];   // 512 MB (time-major: [t][b][4H])
__device__ float g_hs0[(size_t)Tt * Bz * Hh];  // 128 MB (layer0 hs, [t][b][H])
__device__ float g_hT[2][Hh][Bz];              // transposed h ping-pong [k][b]
__device__ float4 g_Upk[16 * 128 * 8 * 32 * 4]; // 33.5 MB packed/split U

// software grid barrier state (returns to 0 after each launch: even #flips)
__device__ unsigned g_bar_count = 0;
__device__ unsigned g_bar_sense = 0;

__device__ __forceinline__ void grid_sync(unsigned& sense, unsigned nblocks) {
    __threadfence();
    __syncthreads();
    if (threadIdx.x == 0) {
        const unsigned s = sense ^ 1u;
        sense = s;
        if (atomicAdd(&g_bar_count, 1u) == nblocks - 1u) {
            atomicExch(&g_bar_count, 0u);
            __threadfence();
            atomicExch(&g_bar_sense, s);
        } else {
            while (atomicAdd(&g_bar_sense, 0u) != s) { __nanosleep(64); }
        }
    }
    __syncthreads();
}

// ---------------------------------------------------------------------------
// tf32 helpers
// ---------------------------------------------------------------------------
__device__ __forceinline__ void split_tf32(float x, uint32_t& hi, uint32_t& lo) {
    uint32_t h;
    asm("cvt.rna.tf32.f32 %0, %1;" : "=r"(h) : "f"(x));
    const float hf = __uint_as_float(h);
    const float lf = x - hf;
    uint32_t l;
    asm("cvt.rna.tf32.f32 %0, %1;" : "=r"(l) : "f"(lf));
    hi = h; lo = l;
}

__device__ __forceinline__ void mma_tf32(float* c, const uint32_t* a, const uint32_t* b) {
    asm volatile(
        "mma.sync.aligned.m16n8k8.row.col.f32.tf32.tf32.f32 "
        "{%0,%1,%2,%3}, {%4,%5,%6,%7}, {%8,%9}, {%0,%1,%2,%3};"
        : "+f"(c[0]), "+f"(c[1]), "+f"(c[2]), "+f"(c[3])
        : "r"(a[0]), "r"(a[1]), "r"(a[2]), "r"(a[3]), "r"(b[0]), "r"(b[1]));
}

__device__ __forceinline__ void cp16(void* dst_smem, const void* src) {
    uint32_t d = (uint32_t)__cvta_generic_to_shared(dst_smem);
    asm volatile("cp.async.cg.shared.global [%0], [%1], 16;" :: "r"(d), "l"(src));
}
#define CP_COMMIT() asm volatile("cp.async.commit_group;")
#define CP_WAIT0()  asm volatile("cp.async.wait_group 0;")

// ---------------------------------------------------------------------------
// Tensor-core GEMM (3xTF32 split): xz = A @ W + bias   (unchanged, proven)
// ---------------------------------------------------------------------------
#define SMP 136

__global__ void __launch_bounds__(256) gemm_xz_kernel(
    const float* __restrict__ Aext, const float* __restrict__ W,
    const float* __restrict__ bias, int layer0)
{
    __shared__ uint32_t As_hi[16][SMP];
    __shared__ uint32_t As_lo[16][SMP];
    __shared__ uint32_t Bs_hi[16][SMP];
    __shared__ uint32_t Bs_lo[16][SMP];

    const int tid = threadIdx.x;
    const int bm = blockIdx.y * 128;
    const int bn = blockIdx.x * 128;

    const int wid = tid >> 5;
    const int lane = tid & 31;
    const int wm = wid >> 2;
    const int wn = wid & 3;
    const int gid = lane >> 2;
    const int tig = lane & 3;

    const int aRow = tid >> 1;
    const int aCol = (tid & 1) << 3;
    const float* aptr;
    {
        const int m = bm + aRow;
        if (layer0) aptr = Aext + ((size_t)(m & 63) * Tt + (m >> 6)) * Dd;
        else        aptr = g_hs0 + (size_t)m * Hh;
    }
    const int bRow = tid >> 4;
    const int bCol = (tid & 15) << 3;
    const float* wptr = W + (size_t)bRow * G4 + bn + bCol;

    float4 ra0 = *(const float4*)(aptr + aCol);
    float4 ra1 = *(const float4*)(aptr + aCol + 4);
    float4 rb0 = *(const float4*)(wptr);
    float4 rb1 = *(const float4*)(wptr + 4);

    float acc[4][4][4];
#pragma unroll
    for (int i = 0; i < 4; i++)
#pragma unroll
        for (int j = 0; j < 4; j++)
#pragma unroll
            for (int q = 0; q < 4; q++) acc[i][j][q] = 0.0f;

    {
        const float av[8] = {ra0.x, ra0.y, ra0.z, ra0.w, ra1.x, ra1.y, ra1.z, ra1.w};
        const float bv[8] = {rb0.x, rb0.y, rb0.z, rb0.w, rb1.x, rb1.y, rb1.z, rb1.w};
#pragma unroll
        for (int j = 0; j < 8; j++) {
            uint32_t h, l;
            split_tf32(av[j], h, l);
            As_hi[aCol + j][aRow] = h; As_lo[aCol + j][aRow] = l;
            split_tf32(bv[j], h, l);
            Bs_hi[bRow][bCol + j] = h; Bs_lo[bRow][bCol + j] = l;
        }
    }
    __syncthreads();

    for (int k0 = 0; k0 < 1024; k0 += 16) {
        const bool more = (k0 + 16 < 1024);
        if (more) {
            ra0 = *(const float4*)(aptr + k0 + 16 + aCol);
            ra1 = *(const float4*)(aptr + k0 + 16 + aCol + 4);
            rb0 = *(const float4*)(wptr + (size_t)(k0 + 16) * G4);
            rb1 = *(const float4*)(wptr + (size_t)(k0 + 16) * G4 + 4);
        }
#pragma unroll
        for (int s = 0; s < 2; s++) {
            const int ks = s * 8;
            uint32_t a_hi[4][4], a_lo[4][4], b_hi[4][2], b_lo[4][2];
#pragma unroll
            for (int mt = 0; mt < 4; mt++) {
                const int m = wm * 64 + mt * 16 + gid;
                a_hi[mt][0] = As_hi[ks + tig][m];
                a_hi[mt][1] = As_hi[ks + tig][m + 8];
                a_hi[mt][2] = As_hi[ks + tig + 4][m];
                a_hi[mt][3] = As_hi[ks + tig + 4][m + 8];
                a_lo[mt][0] = As_lo[ks + tig][m];
                a_lo[mt][1] = As_lo[ks + tig][m + 8];
                a_lo[mt][2] = As_lo[ks + tig + 4][m];
                a_lo[mt][3] = As_lo[ks + tig + 4][m + 8];
            }
#pragma unroll
            for (int nt = 0; nt < 4; nt++) {
                const int n = wn * 32 + nt * 8 + gid;
                b_hi[nt][0] = Bs_hi[ks + tig][n];
                b_hi[nt][1] = Bs_hi[ks + tig + 4][n];
                b_lo[nt][0] = Bs_lo[ks + tig][n];
                b_lo[nt][1] = Bs_lo[ks + tig + 4][n];
            }
#pragma unroll
            for (int mt = 0; mt < 4; mt++)
#pragma unroll
                for (int nt = 0; nt < 4; nt++) {
                    mma_tf32(acc[mt][nt], a_hi[mt], b_hi[nt]);
                    mma_tf32(acc[mt][nt], a_hi[mt], b_lo[nt]);
                    mma_tf32(acc[mt][nt], a_lo[mt], b_hi[nt]);
                }
        }
        __syncthreads();
        if (more) {
            const float av[8] = {ra0.x, ra0.y, ra0.z, ra0.w, ra1.x, ra1.y, ra1.z, ra1.w};
            const float bv[8] = {rb0.x, rb0.y, rb0.z, rb0.w, rb1.x, rb1.y, rb1.z, rb1.w};
#pragma unroll
            for (int j = 0; j < 8; j++) {
                uint32_t h, l;
                split_tf32(av[j], h, l);
                As_hi[aCol + j][aRow] = h; As_lo[aCol + j][aRow] = l;
                split_tf32(bv[j], h, l);
                Bs_hi[bRow][bCol + j] = h; Bs_lo[bRow][bCol + j] = l;
            }
            __syncthreads();
        }
    }

#pragma unroll
    for (int mt = 0; mt < 4; mt++) {
#pragma unroll
        for (int nt = 0; nt < 4; nt++) {
            const int gn = bn + wn * 32 + nt * 8 + 2 * tig;
            const float b0v = bias[gn];
            const float b1v = bias[gn + 1];
            const int r0 = bm + wm * 64 + mt * 16 + gid;
            float* p0 = g_xz + (size_t)r0 * G4 + gn;
            float* p1 = g_xz + (size_t)(r0 + 8) * G4 + gn;
            p0[0] = acc[mt][nt][0] + b0v;
            p0[1] = acc[mt][nt][1] + b1v;
            p1[0] = acc[mt][nt][2] + b0v;
            p1[1] = acc[mt][nt][3] + b1v;
        }
    }
}

// ---------------------------------------------------------------------------
// U prep (unchanged layout, proven):
// [chunk c (16)][block (128)][k8 (8)][n (32)][tig (4)] as float4
//   float4 = ( hi(kt), lo(kt), hi(kt+4), lo(kt+4) ), kt = c*64 + k8*8 + tig
//   n: gate = n>>3, jj = n&7 -> U col = gate*1024 + blk*8 + jj
// ---------------------------------------------------------------------------
__global__ void __launch_bounds__(256) prep_upk_kernel(const float* __restrict__ U) {
    const int i = blockIdx.x * 256 + threadIdx.x;   // 0 .. 2097151
    const int tig = i & 3;
    const int n   = (i >> 2) & 31;
    const int k8  = (i >> 7) & 7;
    const int blk = (i >> 10) & 127;
    const int c   = i >> 17;
    const int kt = c * 64 + k8 * 8 + tig;
    const int gate = n >> 3, jj = n & 7;
    const int gcol = gate * Hh + blk * 8 + jj;
    const float u1 = U[(size_t)kt * G4 + gcol];
    const float u2 = U[(size_t)(kt + 4) * G4 + gcol];
    uint32_t h1, l1, h2, l2;
    split_tf32(u1, h1, l1);
    split_tf32(u2, h2, l2);
    g_Upk[i] = make_float4(__uint_as_float(h1), __uint_as_float(l1),
                           __uint_as_float(h2), __uint_as_float(l2));
}

// ---------------------------------------------------------------------------
// Persistent tensor-core LSTM scan, v2.
// 128 blocks x 256 threads (8 warps, 2 per SMSP).
// K-split: warps 0-3 (kw=0) handle k chunks 0..7, warps 4-7 (kw=1) chunks 8..15.
// Warp w4 = wid&3 covers batch rows 16*w4..16*w4+15; block covers 32 gate-cols
// (hidden cols j0..j0+7 x 4 gates), nt == gate.
// 2-pass tf32: A = raw fp32 h bits (HW truncation), B = pre-split U hi/lo.
// Independent accH/accL chains; kw=1 accs reduced into kw=0 via smem.
// c-state and prev-h in registers of warps 0-3 for all 512 steps.
// ---------------------------------------------------------------------------
#define HST 72                           // h smem row stride (floats)
#define HGRP (64 * HST)                  // 4608 floats per h stage
#define SM_H_FLOATS (2 * 2 * HGRP)       // 18432 floats
#define SM_U_FLOAT4 (2 * 2 * 1024)       // 4096 float4
#define SM_RED_FLOATS 2048               // red[q(16)][w4(4)][lane(32)]
#define SCAN_SMEM ((SM_H_FLOATS + SM_RED_FLOATS) * 4 + SM_U_FLOAT4 * 16)  // 147456 B

__global__ void __launch_bounds__(256, 1) lstm_scan_tc(
    const int* __restrict__ lengths, float* __restrict__ out_base,
    float* __restrict__ out_tail, int layer)
{
    extern __shared__ float sm[];
    float* hbase = sm;                                   // [kw][stage][64][HST]
    float4* ubase = (float4*)(sm + SM_H_FLOATS);         // [kw][stage][1024]
    float* red = sm + SM_H_FLOATS + SM_U_FLOAT4 * 4;     // 2048 floats

    const int tid = threadIdx.x;
    const int blk = blockIdx.x;
    const int wid = tid >> 5;
    const int lane = tid & 31;
    const int gid = lane >> 2;
    const int tig = lane & 3;
    const int kw = tid >> 7;          // 0 or 1 (k-half)
    const int gtid = tid & 127;       // tid within group
    const int w4 = wid & 3;           // warp within group -> batch rows
    const int j0 = blk * 8;
    unsigned sense = 0;

    float* hgrp = hbase + kw * (2 * HGRP);
    float4* ugrp = ubase + kw * (2 * 1024);

    // zero g_hT[0] (initial h state): 65536 floats over 128x256 threads
    {
        const int base = (blk * 256 + tid) * 2;
        *(float2*)&(((float*)g_hT)[base]) = make_float2(0.f, 0.f);
    }

    const int b0 = w4 * 16 + gid;
    const int b1 = b0 + 8;
    const int jA = j0 + 2 * tig;
    int len0 = 0, len1 = 0;
    if (kw == 0) { len0 = lengths[b0]; len1 = lengths[b1]; }

    float cb[4] = {0.f, 0.f, 0.f, 0.f};   // cell state (regs, warps 0-3)
    float hp[4] = {0.f, 0.f, 0.f, 0.f};   // prev h (regs, warps 0-3)

    grid_sync(sense, gridDim.x);   // sync #1 (h0 zeros visible)

    // copy-chunk mappings
    const int hk = gtid >> 1;                 // h row 0..63
    const int hboff = (gtid & 1) * 32;        // 32 floats per thread

    for (int t = 0; t < Tt; t++) {
        // xz prefetch (independent of h -> issue before the barrier)
        const float* xz = g_xz + (size_t)t * (Bz * G4);
        float2 xv[4][2];
        if (kw == 0) {
#pragma unroll
            for (int g = 0; g < 4; g++) {
                xv[g][0] = *(const float2*)(xz + (size_t)b0 * G4 + g * Hh + jA);
                xv[g][1] = *(const float2*)(xz + (size_t)b1 * G4 + g * Hh + jA);
            }
        }
        if (t) grid_sync(sense, gridDim.x);
        const int par = t & 1;

        float accH[4][4], accL[4][4];
#pragma unroll
        for (int nt = 0; nt < 4; nt++)
#pragma unroll
            for (int q = 0; q < 4; q++) { accH[nt][q] = 0.0f; accL[nt][q] = 0.0f; }

        // k loop: this group's 8 chunks of K=64, cp.async double-buffered
        {
            const int cg = kw * 8;
            const float* hsrc = &g_hT[par][cg * 64 + hk][hboff];
            float* hdst = hgrp + hk * HST + hboff;
#pragma unroll
            for (int q = 0; q < 8; q++) cp16(hdst + q * 4, hsrc + q * 4);
            const float4* usrc = g_Upk + ((size_t)cg * 128 + blk) * 1024 + gtid * 8;
            float4* udst = ugrp + gtid * 8;
#pragma unroll
            for (int q = 0; q < 8; q++) cp16(udst + q, usrc + q);
        }
        CP_COMMIT();

        for (int c = 0; c < 8; c++) {
            const int s = c & 1;
            CP_WAIT0();
            __syncthreads();
            if (c < 7) {
                const int cg = kw * 8 + c + 1;
                const int sn = s ^ 1;
                const float* hsrc = &g_hT[par][cg * 64 + hk][hboff];
                float* hdst = hgrp + sn * HGRP + hk * HST + hboff;
#pragma unroll
                for (int q = 0; q < 8; q++) cp16(hdst + q * 4, hsrc + q * 4);
                const float4* usrc = g_Upk + ((size_t)cg * 128 + blk) * 1024 + gtid * 8;
                float4* udst = ugrp + sn * 1024 + gtid * 8;
#pragma unroll
                for (int q = 0; q < 8; q++) cp16(udst + q, usrc + q);
                CP_COMMIT();
            }

            const float* hb = hgrp + s * HGRP;
            const float4* ub = ugrp + s * 1024;
#pragma unroll
            for (int k8 = 0; k8 < 8; k8++) {
                uint32_t ah[4];
                ah[0] = __float_as_uint(hb[(k8 * 8 + tig) * HST + b0]);
                ah[1] = __float_as_uint(hb[(k8 * 8 + tig) * HST + b1]);
                ah[2] = __float_as_uint(hb[(k8 * 8 + tig + 4) * HST + b0]);
                ah[3] = __float_as_uint(hb[(k8 * 8 + tig + 4) * HST + b1]);
#pragma unroll
                for (int nt = 0; nt < 4; nt++) {
                    const float4 bv = ub[(k8 * 32 + nt * 8 + gid) * 4 + tig];
                    uint32_t bh[2], bl[2];
                    bh[0] = __float_as_uint(bv.x); bh[1] = __float_as_uint(bv.z);
                    bl[0] = __float_as_uint(bv.y); bl[1] = __float_as_uint(bv.w);
                    mma_tf32(accH[nt], ah, bh);
                    mma_tf32(accL[nt], ah, bl);
                }
            }
        }
        __syncthreads();

        // k-split reduction: kw=1 writes its partial sums, kw=0 adds them
        if (kw == 1) {
#pragma unroll
            for (int nt = 0; nt < 4; nt++)
#pragma unroll
                for (int q = 0; q < 4; q++)
                    red[(nt * 4 + q) * 128 + w4 * 32 + lane] = accH[nt][q] + accL[nt][q];
        }
        __syncthreads();

        if (kw == 0) {
            float zg4[4][4];
#pragma unroll
            for (int nt = 0; nt < 4; nt++)
#pragma unroll
                for (int q = 0; q < 4; q++)
                    zg4[nt][q] = accH[nt][q] + accL[nt][q]
                               + red[(nt * 4 + q) * 128 + w4 * 32 + lane];

            // gates + state update, all in registers
#pragma unroll
            for (int q = 0; q < 4; q++) {
                const int r = q >> 1;        // 0: row b0, 1: row b1
                const int ccsel = q & 1;     // 0: jA, 1: jA+1
                const float xi = ccsel ? xv[0][r].y : xv[0][r].x;
                const float xf = ccsel ? xv[1][r].y : xv[1][r].x;
                const float xg = ccsel ? xv[2][r].y : xv[2][r].x;
                const float xo = ccsel ? xv[3][r].y : xv[3][r].x;

                const float zi = zg4[0][q] + xi;
                const float zf = zg4[1][q] + xf;
                const float zgg = zg4[2][q] + xg;
                const float zo = zg4[3][q] + xo;

                const float ig = 1.0f / (1.0f + __expf(-zi));
                const float fg = 1.0f / (1.0f + __expf(-zf));
                const float gg = tanhf(zgg);
                const float og = 1.0f / (1.0f + __expf(-zo));

                const float cn = fg * cb[q] + ig * gg;
                const float hn = og * tanhf(cn);

                const bool msk = t < (r ? len1 : len0);
                const float h2 = msk ? hn : hp[q];
                const float c2 = msk ? cn : cb[q];
                hp[q] = h2; cb[q] = c2;

                const int b = r ? b1 : b0;
                const int j = jA + ccsel;
                __stcg(&g_hT[par ^ 1][j][b], h2);
                if (layer == 0) {
                    g_hs0[(size_t)t * (Bz * Hh) + (size_t)b * Hh + j] = h2;
                } else {
                    out_base[(size_t)b * ((size_t)Tt * Hh) + (size_t)t * Hh + j] = h2;
                }
            }
        }
        // total grid_syncs per launch: 512 (even) -> barrier state returns to 0
    }

    // final h, c (post-mask register state, warps 0-3)
    if (layer && kw == 0) {
#pragma unroll
        for (int q = 0; q < 4; q++) {
            const int b = (q >> 1) ? b1 : b0;
            const int j = jA + (q & 1);
            out_tail[(size_t)b * Hh + j] = hp[q];
            out_tail[(size_t)Bz * Hh + (size_t)b * Hh + j] = cb[q];
        }
    }
}

// ---------------------------------------------------------------------------
// Launch: 6 graph nodes
// ---------------------------------------------------------------------------
extern "C" void kernel_launch(void* const* d_in, const int* in_sizes, int n_in,
                              void* d_out, int out_size) {
    (void)in_sizes; (void)n_in; (void)out_size;
    const float* x  = (const float*)d_in[0];
    const int* lens = (const int*)d_in[1];
    const float* W0 = (const float*)d_in[2];
    const float* U0 = (const float*)d_in[3];
    const float* b0 = (const float*)d_in[4];
    const float* W1 = (const float*)d_in[5];
    const float* U1 = (const float*)d_in[6];
    const float* b1 = (const float*)d_in[7];
    float* out = (float*)d_out;

    cudaFuncSetAttribute(lstm_scan_tc,
                         cudaFuncAttributeMaxDynamicSharedMemorySize, SCAN_SMEM);

    const dim3 ggrid(G4 / 128, (Tt * Bz) / 128);   // 32 x 256

    // Layer 0
    gemm_xz_kernel<<<ggrid, 256>>>(x, W0, b0, 1);
    prep_upk_kernel<<<8192, 256>>>(U0);
    lstm_scan_tc<<<128, 256, SCAN_SMEM>>>(lens, nullptr, nullptr, 0);

    // Layer 1
    gemm_xz_kernel<<<ggrid, 256>>>(nullptr, W1, b1, 0);
    prep_upk_kernel<<<8192, 256>>>(U1);
    float* tail = out + (size_t)Bz * Tt * Hh;
    lstm_scan_tc<<<128, 256, SCAN_SMEM>>>(lens, out, tail, 1);
}

// round 11
// speedup vs baseline: 1.3118x; 1.0542x over previous
#include <cuda_runtime.h>
#include <math.h>
#include <stdint.h>

#define Bz 64
#define Tt 512
#define Dd 1024
#define Hh 1024
#define G4 4096

__device__ float g_xz[(size_t)Tt * Bz * G4];
__device__ float g_hs0[(size_t)Tt * Bz * Hh];
__device__ float g_hT[2][Hh][Bz];
__device__ float4 g_Upk[16 * 128 * 8 * 32 * 4];

__device__ unsigned g_bar_count = 0;
__device__ unsigned g_bar_sense = 0;

__device__ __forceinline__ void grid_sync(unsigned& sense, unsigned nblocks) {
    __threadfence();
    __syncthreads();
    if (threadIdx.x == 0) {
        const unsigned s = sense ^ 1u;
        sense = s;
        if (atomicAdd(&g_bar_count, 1u) == nblocks - 1u) {
            atomicExch(&g_bar_count, 0u);
            __threadfence();
            atomicExch(&g_bar_sense, s);
        } else {
            while (atomicAdd(&g_bar_sense, 0u) != s) { __nanosleep(64); }
        }
    }
    __syncthreads();
}

__device__ __forceinline__ void split_tf32(float x, uint32_t& hi, uint32_t& lo) {
    uint32_t h;
    asm("cvt.rna.tf32.f32 %0, %1;" : "=r"(h) : "f"(x));
    const float hf = __uint_as_float(h);
    const float lf = x - hf;
    uint32_t l;
    asm("cvt.rna.tf32.f32 %0, %1;" : "=r"(l) : "f"(lf));
    hi = h; lo = l;
}

__device__ __forceinline__ void mma_tf32(float* c, const uint32_t* a, const uint32_t* b) {
    asm volatile(
        "mma.sync.aligned.m16n8k8.row.col.f32.tf32.tf32.f32 "
        "{%0,%1,%2,%3}, {%4,%5,%6,%7}, {%8,%9}, {%0,%1,%2,%3};"
        : "+f"(c[0]), "+f"(c[1]), "+f"(c[2]), "+f"(c[3])
        : "r"(a[0]), "r"(a[1]), "r"(a[2]), "r"(a[3]), "r"(b[0]), "r"(b[1]));
}

__device__ __forceinline__ void cp16(void* dst_smem, const void* src) {
    uint32_t d = (uint32_t)__cvta_generic_to_shared(dst_smem);
    asm volatile("cp.async.cg.shared.global [%0], [%1], 16;" :: "r"(d), "l"(src));
}
#define CP_COMMIT() asm volatile("cp.async.commit_group;")
#define CP_WAIT0()  asm volatile("cp.async.wait_group 0;")

// ---------------------------------------------------------------------------
// GEMM v2: cp.async double-buffered, split->tf32 at frag load (same math as R8)
// ---------------------------------------------------------------------------
#define APAD 20
#define WPAD 136

__global__ void __launch_bounds__(256) gemm_xz_kernel(
    const float* __restrict__ Aext, const float* __restrict__ W,
    const float* __restrict__ bias, int layer0)
{
    __shared__ __align__(16) float As[2][128][APAD];
    __shared__ __align__(16) float Ws[2][16][WPAD];

    const int tid = threadIdx.x;
    const int bm = blockIdx.y * 128;
    const int bn = blockIdx.x * 128;

    const int wid = tid >> 5;
    const int lane = tid & 31;
    const int wm = wid >> 2;
    const int wn = wid & 3;
    const int gid = lane >> 2;
    const int tig = lane & 3;

    const int aRow = tid >> 1;
    const int aOff = (tid & 1) << 3;
    const float* aptr;
    {
        const int m = bm + aRow;
        if (layer0) aptr = Aext + ((size_t)(m & 63) * Tt + (m >> 6)) * Dd;
        else        aptr = g_hs0 + (size_t)m * Hh;
    }
    const int wRow = tid >> 4;
    const int wOff = (tid & 15) << 3;
    const float* wptr = W + (size_t)wRow * G4 + bn + wOff;

    cp16(&As[0][aRow][aOff],     aptr + aOff);
    cp16(&As[0][aRow][aOff + 4], aptr + aOff + 4);
    cp16(&Ws[0][wRow][wOff],     wptr);
    cp16(&Ws[0][wRow][wOff + 4], wptr + 4);
    CP_COMMIT();

    float acc[4][4][4];
#pragma unroll
    for (int i = 0; i < 4; i++)
#pragma unroll
        for (int j = 0; j < 4; j++)
#pragma unroll
            for (int q = 0; q < 4; q++) acc[i][j][q] = 0.0f;

    for (int k0 = 0; k0 < 1024; k0 += 16) {
        CP_WAIT0();
        __syncthreads();
        const int buf = (k0 >> 4) & 1;
        if (k0 + 16 < 1024) {
            const int nb = buf ^ 1;
            const float* an = aptr + k0 + 16;
            const float* wn_ = wptr + (size_t)(k0 + 16) * G4;
            cp16(&As[nb][aRow][aOff],     an + aOff);
            cp16(&As[nb][aRow][aOff + 4], an + aOff + 4);
            cp16(&Ws[nb][wRow][wOff],     wn_);
            cp16(&Ws[nb][wRow][wOff + 4], wn_ + 4);
            CP_COMMIT();
        }

#pragma unroll
        for (int s = 0; s < 2; s++) {
            const int ks = s * 8;
            uint32_t a_hi[4][4], a_lo[4][4], b_hi[4][2], b_lo[4][2];
#pragma unroll
            for (int mt = 0; mt < 4; mt++) {
                const int m = wm * 64 + mt * 16 + gid;
                split_tf32(As[buf][m][ks + tig],         a_hi[mt][0], a_lo[mt][0]);
                split_tf32(As[buf][m + 8][ks + tig],     a_hi[mt][1], a_lo[mt][1]);
                split_tf32(As[buf][m][ks + tig + 4],     a_hi[mt][2], a_lo[mt][2]);
                split_tf32(As[buf][m + 8][ks + tig + 4], a_hi[mt][3], a_lo[mt][3]);
            }
#pragma unroll
            for (int nt = 0; nt < 4; nt++) {
                const int n = wn * 32 + nt * 8 + gid;
                split_tf32(Ws[buf][ks + tig][n],     b_hi[nt][0], b_lo[nt][0]);
                split_tf32(Ws[buf][ks + tig + 4][n], b_hi[nt][1], b_lo[nt][1]);
            }
#pragma unroll
            for (int mt = 0; mt < 4; mt++)
#pragma unroll
                for (int nt = 0; nt < 4; nt++) {
                    mma_tf32(acc[mt][nt], a_hi[mt], b_hi[nt]);
                    mma_tf32(acc[mt][nt], a_hi[mt], b_lo[nt]);
                    mma_tf32(acc[mt][nt], a_lo[mt], b_hi[nt]);
                }
        }
    }

#pragma unroll
    for (int mt = 0; mt < 4; mt++) {
#pragma unroll
        for (int nt = 0; nt < 4; nt++) {
            const int gn = bn + wn * 32 + nt * 8 + 2 * tig;
            const float b0v = bias[gn];
            const float b1v = bias[gn + 1];
            const int r0 = bm + wm * 64 + mt * 16 + gid;
            float* p0 = g_xz + (size_t)r0 * G4 + gn;
            float* p1 = g_xz + (size_t)(r0 + 8) * G4 + gn;
            p0[0] = acc[mt][nt][0] + b0v;
            p0[1] = acc[mt][nt][1] + b1v;
            p1[0] = acc[mt][nt][2] + b0v;
            p1[1] = acc[mt][nt][3] + b1v;
        }
    }
}

// ---------------------------------------------------------------------------
// U prep (R8 verbatim, proven)
// ---------------------------------------------------------------------------
__global__ void __launch_bounds__(256) prep_upk_kernel(const float* __restrict__ U) {
    const int i = blockIdx.x * 256 + threadIdx.x;
    const int tig = i & 3;
    const int n   = (i >> 2) & 31;
    const int k8  = (i >> 7) & 7;
    const int blk = (i >> 10) & 127;
    const int c   = i >> 17;
    const int kt = c * 64 + k8 * 8 + tig;
    const int gate = n >> 3, jj = n & 7;
    const int gcol = gate * Hh + blk * 8 + jj;
    const float u1 = U[(size_t)kt * G4 + gcol];
    const float u2 = U[(size_t)(kt + 4) * G4 + gcol];
    uint32_t h1, l1, h2, l2;
    split_tf32(u1, h1, l1);
    split_tf32(u2, h2, l2);
    g_Upk[i] = make_float4(__uint_as_float(h1), __uint_as_float(l1),
                           __uint_as_float(h2), __uint_as_float(l2));
}

// ---------------------------------------------------------------------------
// Persistent tf32 scan (R8 verbatim, proven at 41,988us / rel_err 6.2e-4)
// ---------------------------------------------------------------------------
#define HST 72
#define HGRP (64 * HST)
#define SM_H_FLOATS (2 * 2 * HGRP)
#define SM_U_FLOAT4 (2 * 2 * 1024)
#define SM_RED_FLOATS 2048
#define SCAN_SMEM ((SM_H_FLOATS + SM_RED_FLOATS) * 4 + SM_U_FLOAT4 * 16)

__global__ void __launch_bounds__(256, 1) lstm_scan_tc(
    const int* __restrict__ lengths, float* __restrict__ out_base,
    float* __restrict__ out_tail, int layer)
{
    extern __shared__ float sm[];
    float* hbase = sm;
    float4* ubase = (float4*)(sm + SM_H_FLOATS);
    float* red = sm + SM_H_FLOATS + SM_U_FLOAT4 * 4;

    const int tid = threadIdx.x;
    const int blk = blockIdx.x;
    const int wid = tid >> 5;
    const int lane = tid & 31;
    const int gid = lane >> 2;
    const int tig = lane & 3;
    const int kw = tid >> 7;
    const int gtid = tid & 127;
    const int w4 = wid & 3;
    const int j0 = blk * 8;
    unsigned sense = 0;

    float* hgrp = hbase + kw * (2 * HGRP);
    float4* ugrp = ubase + kw * (2 * 1024);

    {
        const int base = (blk * 256 + tid) * 2;
        *(float2*)&(((float*)g_hT)[base]) = make_float2(0.f, 0.f);
    }

    const int b0 = w4 * 16 + gid;
    const int b1 = b0 + 8;
    const int jA = j0 + 2 * tig;
    int len0 = 0, len1 = 0;
    if (kw == 0) { len0 = lengths[b0]; len1 = lengths[b1]; }

    float cb[4] = {0.f, 0.f, 0.f, 0.f};
    float hp[4] = {0.f, 0.f, 0.f, 0.f};

    grid_sync(sense, gridDim.x);

    const int hk = gtid >> 1;
    const int hboff = (gtid & 1) * 32;

    for (int t = 0; t < Tt; t++) {
        const float* xz = g_xz + (size_t)t * (Bz * G4);
        float2 xv[4][2];
        if (kw == 0) {
#pragma unroll
            for (int g = 0; g < 4; g++) {
                xv[g][0] = *(const float2*)(xz + (size_t)b0 * G4 + g * Hh + jA);
                xv[g][1] = *(const float2*)(xz + (size_t)b1 * G4 + g * Hh + jA);
            }
        }
        if (t) grid_sync(sense, gridDim.x);
        const int par = t & 1;

        float accH[4][4], accL[4][4];
#pragma unroll
        for (int nt = 0; nt < 4; nt++)
#pragma unroll
            for (int q = 0; q < 4; q++) { accH[nt][q] = 0.0f; accL[nt][q] = 0.0f; }

        {
            const int cg = kw * 8;
            const float* hsrc = &g_hT[par][cg * 64 + hk][hboff];
            float* hdst = hgrp + hk * HST + hboff;
#pragma unroll
            for (int q = 0; q < 8; q++) cp16(hdst + q * 4, hsrc + q * 4);
            const float4* usrc = g_Upk + ((size_t)cg * 128 + blk) * 1024 + gtid * 8;
            float4* udst = ugrp + gtid * 8;
#pragma unroll
            for (int q = 0; q < 8; q++) cp16(udst + q, usrc + q);
        }
        CP_COMMIT();

        for (int c = 0; c < 8; c++) {
            const int s = c & 1;
            CP_WAIT0();
            __syncthreads();
            if (c < 7) {
                const int cg = kw * 8 + c + 1;
                const int sn = s ^ 1;
                const float* hsrc = &g_hT[par][cg * 64 + hk][hboff];
                float* hdst = hgrp + sn * HGRP + hk * HST + hboff;
#pragma unroll
                for (int q = 0; q < 8; q++) cp16(hdst + q * 4, hsrc + q * 4);
                const float4* usrc = g_Upk + ((size_t)cg * 128 + blk) * 1024 + gtid * 8;
                float4* udst = ugrp + sn * 1024 + gtid * 8;
#pragma unroll
                for (int q = 0; q < 8; q++) cp16(udst + q, usrc + q);
                CP_COMMIT();
            }

            const float* hb = hgrp + s * HGRP;
            const float4* ub = ugrp + s * 1024;
#pragma unroll
            for (int k8 = 0; k8 < 8; k8++) {
                uint32_t ah[4];
                ah[0] = __float_as_uint(hb[(k8 * 8 + tig) * HST + b0]);
                ah[1] = __float_as_uint(hb[(k8 * 8 + tig) * HST + b1]);
                ah[2] = __float_as_uint(hb[(k8 * 8 + tig + 4) * HST + b0]);
                ah[3] = __float_as_uint(hb[(k8 * 8 + tig + 4) * HST + b1]);
#pragma unroll
                for (int nt = 0; nt < 4; nt++) {
                    const float4 bv = ub[(k8 * 32 + nt * 8 + gid) * 4 + tig];
                    uint32_t bh[2], bl[2];
                    bh[0] = __float_as_uint(bv.x); bh[1] = __float_as_uint(bv.z);
                    bl[0] = __float_as_uint(bv.y); bl[1] = __float_as_uint(bv.w);
                    mma_tf32(accH[nt], ah, bh);
                    mma_tf32(accL[nt], ah, bl);
                }
            }
        }
        __syncthreads();

        if (kw == 1) {
#pragma unroll
            for (int nt = 0; nt < 4; nt++)
#pragma unroll
                for (int q = 0; q < 4; q++)
                    red[(nt * 4 + q) * 128 + w4 * 32 + lane] = accH[nt][q] + accL[nt][q];
        }
        __syncthreads();

        if (kw == 0) {
            float zg4[4][4];
#pragma unroll
            for (int nt = 0; nt < 4; nt++)
#pragma unroll
                for (int q = 0; q < 4; q++)
                    zg4[nt][q] = accH[nt][q] + accL[nt][q]
                               + red[(nt * 4 + q) * 128 + w4 * 32 + lane];

#pragma unroll
            for (int q = 0; q < 4; q++) {
                const int r = q >> 1;
                const int ccsel = q & 1;
                const float xi = ccsel ? xv[0][r].y : xv[0][r].x;
                const float xf = ccsel ? xv[1][r].y : xv[1][r].x;
                const float xg = ccsel ? xv[2][r].y : xv[2][r].x;
                const float xo = ccsel ? xv[3][r].y : xv[3][r].x;

                const float zi = zg4[0][q] + xi;
                const float zf = zg4[1][q] + xf;
                const float zgg = zg4[2][q] + xg;
                const float zo = zg4[3][q] + xo;

                const float ig = 1.0f / (1.0f + __expf(-zi));
                const float fg = 1.0f / (1.0f + __expf(-zf));
                const float gg = tanhf(zgg);
                const float og = 1.0f / (1.0f + __expf(-zo));

                const float cn = fg * cb[q] + ig * gg;
                const float hn = og * tanhf(cn);

                const bool msk = t < (r ? len1 : len0);
                const float h2 = msk ? hn : hp[q];
                const float c2 = msk ? cn : cb[q];
                hp[q] = h2; cb[q] = c2;

                const int b = r ? b1 : b0;
                const int j = jA + ccsel;
                __stcg(&g_hT[par ^ 1][j][b], h2);
                if (layer == 0) {
                    g_hs0[(size_t)t * (Bz * Hh) + (size_t)b * Hh + j] = h2;
                } else {
                    out_base[(size_t)b * ((size_t)Tt * Hh) + (size_t)t * Hh + j] = h2;
                }
            }
        }
    }

    if (layer && kw == 0) {
#pragma unroll
        for (int q = 0; q < 4; q++) {
            const int b = (q >> 1) ? b1 : b0;
            const int j = jA + (q & 1);
            out_tail[(size_t)b * Hh + j] = hp[q];
            out_tail[(size_t)Bz * Hh + (size_t)b * Hh + j] = cb[q];
        }
    }
}

extern "C" void kernel_launch(void* const* d_in, const int* in_sizes, int n_in,
                              void* d_out, int out_size) {
    (void)in_sizes; (void)n_in; (void)out_size;
    const float* x  = (const float*)d_in[0];
    const int* lens = (const int*)d_in[1];
    const float* W0 = (const float*)d_in[2];
    const float* U0 = (const float*)d_in[3];
    const float* b0 = (const float*)d_in[4];
    const float* W1 = (const float*)d_in[5];
    const float* U1 = (const float*)d_in[6];
    const float* b1 = (const float*)d_in[7];
    float* out = (float*)d_out;

    cudaFuncSetAttribute(lstm_scan_tc,
                         cudaFuncAttributeMaxDynamicSharedMemorySize, SCAN_SMEM);

    const dim3 ggrid(G4 / 128, (Tt * Bz) / 128);

    gemm_xz_kernel<<<ggrid, 256>>>(x, W0, b0, 1);
    prep_upk_kernel<<<8192, 256>>>(U0);
    lstm_scan_tc<<<128, 256, SCAN_SMEM>>>(lens, nullptr, nullptr, 0);

    gemm_xz_kernel<<<ggrid, 256>>>(nullptr, W1, b1, 0);
    prep_upk_kernel<<<8192, 256>>>(U1);
    float* tail = out + (size_t)Bz * Tt * Hh;
    lstm_scan_tc<<<128, 256, SCAN_SMEM>>>(lens, out, tail, 1);
}

// round 13
// speedup vs baseline: 1.3964x; 1.0645x over previous
#include <cuda_runtime.h>
#include <math.h>
#include <stdint.h>

#define Bz 64
#define Tt 512
#define Dd 1024
#define Hh 1024
#define G4 4096

__device__ float g_xz[(size_t)Tt * Bz * G4];
__device__ float g_hs0[(size_t)Tt * Bz * Hh];
__device__ float g_hT[2][Hh][Bz];
__device__ float4 g_Upk[16 * 128 * 8 * 32 * 4];

__device__ unsigned g_bar_count = 0;
__device__ unsigned g_bar_sense = 0;

// sense-reversing barrier, atomic-poll (R8/R11-proven; cg-poll variant CORRUPTS)
__device__ __forceinline__ void grid_sync(unsigned& sense, unsigned nblocks) {
    __threadfence();
    __syncthreads();
    if (threadIdx.x == 0) {
        const unsigned s = sense ^ 1u;
        sense = s;
        if (atomicAdd(&g_bar_count, 1u) == nblocks - 1u) {
            atomicExch(&g_bar_count, 0u);
            __threadfence();
            atomicExch(&g_bar_sense, s);
        } else {
            while (atomicAdd(&g_bar_sense, 0u) != s) { __nanosleep(64); }
        }
    }
    __syncthreads();
}

__device__ __forceinline__ void split_tf32(float x, uint32_t& hi, uint32_t& lo) {
    uint32_t h;
    asm("cvt.rna.tf32.f32 %0, %1;" : "=r"(h) : "f"(x));
    const float hf = __uint_as_float(h);
    const float lf = x - hf;
    uint32_t l;
    asm("cvt.rna.tf32.f32 %0, %1;" : "=r"(l) : "f"(lf));
    hi = h; lo = l;
}

__device__ __forceinline__ void mma_tf32(float* c, const uint32_t* a, const uint32_t* b) {
    asm volatile(
        "mma.sync.aligned.m16n8k8.row.col.f32.tf32.tf32.f32 "
        "{%0,%1,%2,%3}, {%4,%5,%6,%7}, {%8,%9}, {%0,%1,%2,%3};"
        : "+f"(c[0]), "+f"(c[1]), "+f"(c[2]), "+f"(c[3])
        : "r"(a[0]), "r"(a[1]), "r"(a[2]), "r"(a[3]), "r"(b[0]), "r"(b[1]));
}

__device__ __forceinline__ void cp16(void* dst_smem, const void* src) {
    uint32_t d = (uint32_t)__cvta_generic_to_shared(dst_smem);
    asm volatile("cp.async.cg.shared.global [%0], [%1], 16;" :: "r"(d), "l"(src));
}
#define CP_COMMIT() asm volatile("cp.async.commit_group;")
#define CP_WAIT0()  asm volatile("cp.async.wait_group 0;")
#define CP_WAIT1()  asm volatile("cp.async.wait_group 1;")

// ---------------------------------------------------------------------------
// GEMM (R11 verbatim, proven)
// ---------------------------------------------------------------------------
#define APAD 20
#define WPAD 136

__global__ void __launch_bounds__(256) gemm_xz_kernel(
    const float* __restrict__ Aext, const float* __restrict__ W,
    const float* __restrict__ bias, int layer0)
{
    __shared__ __align__(16) float As[2][128][APAD];
    __shared__ __align__(16) float Ws[2][16][WPAD];

    const int tid = threadIdx.x;
    const int bm = blockIdx.y * 128;
    const int bn = blockIdx.x * 128;

    const int wid = tid >> 5;
    const int lane = tid & 31;
    const int wm = wid >> 2;
    const int wn = wid & 3;
    const int gid = lane >> 2;
    const int tig = lane & 3;

    const int aRow = tid >> 1;
    const int aOff = (tid & 1) << 3;
    const float* aptr;
    {
        const int m = bm + aRow;
        if (layer0) aptr = Aext + ((size_t)(m & 63) * Tt + (m >> 6)) * Dd;
        else        aptr = g_hs0 + (size_t)m * Hh;
    }
    const int wRow = tid >> 4;
    const int wOff = (tid & 15) << 3;
    const float* wptr = W + (size_t)wRow * G4 + bn + wOff;

    cp16(&As[0][aRow][aOff],     aptr + aOff);
    cp16(&As[0][aRow][aOff + 4], aptr + aOff + 4);
    cp16(&Ws[0][wRow][wOff],     wptr);
    cp16(&Ws[0][wRow][wOff + 4], wptr + 4);
    CP_COMMIT();

    float acc[4][4][4];
#pragma unroll
    for (int i = 0; i < 4; i++)
#pragma unroll
        for (int j = 0; j < 4; j++)
#pragma unroll
            for (int q = 0; q < 4; q++) acc[i][j][q] = 0.0f;

    for (int k0 = 0; k0 < 1024; k0 += 16) {
        CP_WAIT0();
        __syncthreads();
        const int buf = (k0 >> 4) & 1;
        if (k0 + 16 < 1024) {
            const int nb = buf ^ 1;
            const float* an = aptr + k0 + 16;
            const float* wn_ = wptr + (size_t)(k0 + 16) * G4;
            cp16(&As[nb][aRow][aOff],     an + aOff);
            cp16(&As[nb][aRow][aOff + 4], an + aOff + 4);
            cp16(&Ws[nb][wRow][wOff],     wn_);
            cp16(&Ws[nb][wRow][wOff + 4], wn_ + 4);
            CP_COMMIT();
        }
#pragma unroll
        for (int s = 0; s < 2; s++) {
            const int ks = s * 8;
            uint32_t a_hi[4][4], a_lo[4][4], b_hi[4][2], b_lo[4][2];
#pragma unroll
            for (int mt = 0; mt < 4; mt++) {
                const int m = wm * 64 + mt * 16 + gid;
                split_tf32(As[buf][m][ks + tig],         a_hi[mt][0], a_lo[mt][0]);
                split_tf32(As[buf][m + 8][ks + tig],     a_hi[mt][1], a_lo[mt][1]);
                split_tf32(As[buf][m][ks + tig + 4],     a_hi[mt][2], a_lo[mt][2]);
                split_tf32(As[buf][m + 8][ks + tig + 4], a_hi[mt][3], a_lo[mt][3]);
            }
#pragma unroll
            for (int nt = 0; nt < 4; nt++) {
                const int n = wn * 32 + nt * 8 + gid;
                split_tf32(Ws[buf][ks + tig][n],     b_hi[nt][0], b_lo[nt][0]);
                split_tf32(Ws[buf][ks + tig + 4][n], b_hi[nt][1], b_lo[nt][1]);
            }
#pragma unroll
            for (int mt = 0; mt < 4; mt++)
#pragma unroll
                for (int nt = 0; nt < 4; nt++) {
                    mma_tf32(acc[mt][nt], a_hi[mt], b_hi[nt]);
                    mma_tf32(acc[mt][nt], a_hi[mt], b_lo[nt]);
                    mma_tf32(acc[mt][nt], a_lo[mt], b_hi[nt]);
                }
        }
    }

#pragma unroll
    for (int mt = 0; mt < 4; mt++) {
#pragma unroll
        for (int nt = 0; nt < 4; nt++) {
            const int gn = bn + wn * 32 + nt * 8 + 2 * tig;
            const float b0v = bias[gn];
            const float b1v = bias[gn + 1];
            const int r0 = bm + wm * 64 + mt * 16 + gid;
            float* p0 = g_xz + (size_t)r0 * G4 + gn;
            float* p1 = g_xz + (size_t)(r0 + 8) * G4 + gn;
            p0[0] = acc[mt][nt][0] + b0v;
            p0[1] = acc[mt][nt][1] + b1v;
            p1[0] = acc[mt][nt][2] + b0v;
            p1[1] = acc[mt][nt][3] + b1v;
        }
    }
}

// ---------------------------------------------------------------------------
// U prep (R8 verbatim, proven)
// ---------------------------------------------------------------------------
__global__ void __launch_bounds__(256) prep_upk_kernel(const float* __restrict__ U) {
    const int i = blockIdx.x * 256 + threadIdx.x;
    const int tig = i & 3;
    const int n   = (i >> 2) & 31;
    const int k8  = (i >> 7) & 7;
    const int blk = (i >> 10) & 127;
    const int c   = i >> 17;
    const int kt = c * 64 + k8 * 8 + tig;
    const int gate = n >> 3, jj = n & 7;
    const int gcol = gate * Hh + blk * 8 + jj;
    const float u1 = U[(size_t)kt * G4 + gcol];
    const float u2 = U[(size_t)(kt + 4) * G4 + gcol];
    uint32_t h1, l1, h2, l2;
    split_tf32(u1, h1, l1);
    split_tf32(u2, h2, l2);
    g_Upk[i] = make_float4(__uint_as_float(h1), __uint_as_float(l1),
                           __uint_as_float(h2), __uint_as_float(l2));
}

// ---------------------------------------------------------------------------
// Persistent tf32 scan: R8 math verbatim; 3-stage cp.async pipeline;
// atomic-poll barrier (the only change vs R12)
// ---------------------------------------------------------------------------
#define HST 72
#define HGRP (64 * HST)
#define SM_H_FLOATS (2 * 3 * HGRP)
#define SM_U_FLOAT4 (2 * 3 * 1024)
#define SM_RED_FLOATS 2048
#define SCAN_SMEM ((SM_H_FLOATS + SM_RED_FLOATS) * 4 + SM_U_FLOAT4 * 16)  // 217088 B

__global__ void __launch_bounds__(256, 1) lstm_scan_tc(
    const int* __restrict__ lengths, float* __restrict__ out_base,
    float* __restrict__ out_tail, int layer)
{
    extern __shared__ float sm[];
    float* hbase = sm;
    float4* ubase = (float4*)(sm + SM_H_FLOATS);
    float* red = sm + SM_H_FLOATS + SM_U_FLOAT4 * 4;

    const int tid = threadIdx.x;
    const int blk = blockIdx.x;
    const int wid = tid >> 5;
    const int lane = tid & 31;
    const int gid = lane >> 2;
    const int tig = lane & 3;
    const int kw = tid >> 7;
    const int gtid = tid & 127;
    const int w4 = wid & 3;
    const int j0 = blk * 8;
    unsigned sense = 0;

    float* hgrp = hbase + kw * (3 * HGRP);
    float4* ugrp = ubase + kw * (3 * 1024);

    {
        const int base = (blk * 256 + tid) * 2;
        *(float2*)&(((float*)g_hT)[base]) = make_float2(0.f, 0.f);
    }

    const int b0 = w4 * 16 + gid;
    const int b1 = b0 + 8;
    const int jA = j0 + 2 * tig;
    int len0 = 0, len1 = 0;
    if (kw == 0) { len0 = lengths[b0]; len1 = lengths[b1]; }

    float cb[4] = {0.f, 0.f, 0.f, 0.f};
    float hp[4] = {0.f, 0.f, 0.f, 0.f};

    grid_sync(sense, gridDim.x);

    const int hk = gtid >> 1;
    const int hboff = (gtid & 1) * 32;

    for (int t = 0; t < Tt; t++) {
        const float* xz = g_xz + (size_t)t * (Bz * G4);
        float2 xv[4][2];
        if (kw == 0) {
#pragma unroll
            for (int g = 0; g < 4; g++) {
                xv[g][0] = *(const float2*)(xz + (size_t)b0 * G4 + g * Hh + jA);
                xv[g][1] = *(const float2*)(xz + (size_t)b1 * G4 + g * Hh + jA);
            }
        }
        if (t) grid_sync(sense, gridDim.x);
        const int par = t & 1;

        float accH[4][4], accL[4][4];
#pragma unroll
        for (int nt = 0; nt < 4; nt++)
#pragma unroll
            for (int q = 0; q < 4; q++) { accH[nt][q] = 0.0f; accL[nt][q] = 0.0f; }

        // issue chunks 0 and 1 (each its own commit group)
#pragma unroll
        for (int p = 0; p < 2; p++) {
            const int cg = kw * 8 + p;
            const float* hsrc = &g_hT[par][cg * 64 + hk][hboff];
            float* hdst = hgrp + p * HGRP + hk * HST + hboff;
#pragma unroll
            for (int q = 0; q < 8; q++) cp16(hdst + q * 4, hsrc + q * 4);
            const float4* usrc = g_Upk + ((size_t)cg * 128 + blk) * 1024 + gtid * 8;
            float4* udst = ugrp + p * 1024 + gtid * 8;
#pragma unroll
            for (int q = 0; q < 8; q++) cp16(udst + q, usrc + q);
            CP_COMMIT();
        }

#pragma unroll
        for (int c = 0; c < 8; c++) {
            const int s = c % 3;
            if (c < 7) { CP_WAIT1(); } else { CP_WAIT0(); }
            __syncthreads();
            if (c < 6) {
                const int cg = kw * 8 + c + 2;
                const int sn = (c + 2) % 3;
                const float* hsrc = &g_hT[par][cg * 64 + hk][hboff];
                float* hdst = hgrp + sn * HGRP + hk * HST + hboff;
#pragma unroll
                for (int q = 0; q < 8; q++) cp16(hdst + q * 4, hsrc + q * 4);
                const float4* usrc = g_Upk + ((size_t)cg * 128 + blk) * 1024 + gtid * 8;
                float4* udst = ugrp + sn * 1024 + gtid * 8;
#pragma unroll
                for (int q = 0; q < 8; q++) cp16(udst + q, usrc + q);
                CP_COMMIT();
            }

            const float* hb = hgrp + s * HGRP;
            const float4* ub = ugrp + s * 1024;
#pragma unroll
            for (int k8 = 0; k8 < 8; k8++) {
                uint32_t ah[4];
                ah[0] = __float_as_uint(hb[(k8 * 8 + tig) * HST + b0]);
                ah[1] = __float_as_uint(hb[(k8 * 8 + tig) * HST + b1]);
                ah[2] = __float_as_uint(hb[(k8 * 8 + tig + 4) * HST + b0]);
                ah[3] = __float_as_uint(hb[(k8 * 8 + tig + 4) * HST + b1]);
#pragma unroll
                for (int nt = 0; nt < 4; nt++) {
                    const float4 bv = ub[(k8 * 32 + nt * 8 + gid) * 4 + tig];
                    uint32_t bh[2], bl[2];
                    bh[0] = __float_as_uint(bv.x); bh[1] = __float_as_uint(bv.z);
                    bl[0] = __float_as_uint(bv.y); bl[1] = __float_as_uint(bv.w);
                    mma_tf32(accH[nt], ah, bh);
                    mma_tf32(accL[nt], ah, bl);
                }
            }
        }
        __syncthreads();

        if (kw == 1) {
#pragma unroll
            for (int nt = 0; nt < 4; nt++)
#pragma unroll
                for (int q = 0; q < 4; q++)
                    red[(nt * 4 + q) * 128 + w4 * 32 + lane] = accH[nt][q] + accL[nt][q];
        }
        __syncthreads();

        if (kw == 0) {
            float zg4[4][4];
#pragma unroll
            for (int nt = 0; nt < 4; nt++)
#pragma unroll
                for (int q = 0; q < 4; q++)
                    zg4[nt][q] = accH[nt][q] + accL[nt][q]
                               + red[(nt * 4 + q) * 128 + w4 * 32 + lane];

#pragma unroll
            for (int q = 0; q < 4; q++) {
                const int r = q >> 1;
                const int ccsel = q & 1;
                const float xi = ccsel ? xv[0][r].y : xv[0][r].x;
                const float xf = ccsel ? xv[1][r].y : xv[1][r].x;
                const float xg = ccsel ? xv[2][r].y : xv[2][r].x;
                const float xo = ccsel ? xv[3][r].y : xv[3][r].x;

                const float zi = zg4[0][q] + xi;
                const float zf = zg4[1][q] + xf;
                const float zgg = zg4[2][q] + xg;
                const float zo = zg4[3][q] + xo;

                const float ig = 1.0f / (1.0f + __expf(-zi));
                const float fg = 1.0f / (1.0f + __expf(-zf));
                const float gg = tanhf(zgg);
                const float og = 1.0f / (1.0f + __expf(-zo));

                const float cn = fg * cb[q] + ig * gg;
                const float hn = og * tanhf(cn);

                const bool msk = t < (r ? len1 : len0);
                const float h2 = msk ? hn : hp[q];
                const float c2 = msk ? cn : cb[q];
                hp[q] = h2; cb[q] = c2;

                const int b = r ? b1 : b0;
                const int j = jA + ccsel;
                __stcg(&g_hT[par ^ 1][j][b], h2);
                if (layer == 0) {
                    g_hs0[(size_t)t * (Bz * Hh) + (size_t)b * Hh + j] = h2;
                } else {
                    out_base[(size_t)b * ((size_t)Tt * Hh) + (size_t)t * Hh + j] = h2;
                }
            }
        }
    }

    if (layer && kw == 0) {
#pragma unroll
        for (int q = 0; q < 4; q++) {
            const int b = (q >> 1) ? b1 : b0;
            const int j = jA + (q & 1);
            out_tail[(size_t)b * Hh + j] = hp[q];
            out_tail[(size_t)Bz * Hh + (size_t)b * Hh + j] = cb[q];
        }
    }
}

extern "C" void kernel_launch(void* const* d_in, const int* in_sizes, int n_in,
                              void* d_out, int out_size) {
    (void)in_sizes; (void)n_in; (void)out_size;
    const float* x  = (const float*)d_in[0];
    const int* lens = (const int*)d_in[1];
    const float* W0 = (const float*)d_in[2];
    const float* U0 = (const float*)d_in[3];
    const float* b0 = (const float*)d_in[4];
    const float* W1 = (const float*)d_in[5];
    const float* U1 = (const float*)d_in[6];
    const float* b1 = (const float*)d_in[7];
    float* out = (float*)d_out;

    cudaFuncSetAttribute(lstm_scan_tc,
                         cudaFuncAttributeMaxDynamicSharedMemorySize, SCAN_SMEM);

    const dim3 ggrid(G4 / 128, (Tt * Bz) / 128);

    gemm_xz_kernel<<<ggrid, 256>>>(x, W0, b0, 1);
    prep_upk_kernel<<<8192, 256>>>(U0);
    lstm_scan_tc<<<128, 256, SCAN_SMEM>>>(lens, nullptr, nullptr, 0);

    gemm_xz_kernel<<<ggrid, 256>>>(nullptr, W1, b1, 0);
    prep_upk_kernel<<<8192, 256>>>(U1);
    float* tail = out + (size_t)Bz * Tt * Hh;
    lstm_scan_tc<<<128, 256, SCAN_SMEM>>>(lens, out, tail, 1);
}

// round 14
// speedup vs baseline: 1.7854x; 1.2785x over previous
#include <cuda_runtime.h>
#include <cuda_bf16.h>
#include <math.h>
#include <stdint.h>

#define Bz 64
#define Tt 512
#define Dd 1024
#define Hh 1024
#define G4 4096

__device__ float g_xz[(size_t)Tt * Bz * G4];
__device__ float g_hs0[(size_t)Tt * Bz * Hh];
__device__ uint32_t g_hP[2][2][512][64];       // [par][hi/lo][k2][b] bf16x2 words
__device__ uint4 g_Upk[1048576];               // 16 MB packed bf16 hi/lo U frags

__device__ unsigned g_bar_count = 0;
__device__ unsigned g_bar_sense = 0;

// sense-reversing barrier, atomic-poll (R8/R11/R13-proven; cg-poll CORRUPTS)
__device__ __forceinline__ void grid_sync(unsigned& sense, unsigned nblocks) {
    __threadfence();
    __syncthreads();
    if (threadIdx.x == 0) {
        const unsigned s = sense ^ 1u;
        sense = s;
        if (atomicAdd(&g_bar_count, 1u) == nblocks - 1u) {
            atomicExch(&g_bar_count, 0u);
            __threadfence();
            atomicExch(&g_bar_sense, s);
        } else {
            while (atomicAdd(&g_bar_sense, 0u) != s) { __nanosleep(64); }
        }
    }
    __syncthreads();
}

__device__ __forceinline__ void split_tf32(float x, uint32_t& hi, uint32_t& lo) {
    uint32_t h;
    asm("cvt.rna.tf32.f32 %0, %1;" : "=r"(h) : "f"(x));
    const float hf = __uint_as_float(h);
    const float lf = x - hf;
    uint32_t l;
    asm("cvt.rna.tf32.f32 %0, %1;" : "=r"(l) : "f"(lf));
    hi = h; lo = l;
}

__device__ __forceinline__ void mma_tf32(float* c, const uint32_t* a, const uint32_t* b) {
    asm volatile(
        "mma.sync.aligned.m16n8k8.row.col.f32.tf32.tf32.f32 "
        "{%0,%1,%2,%3}, {%4,%5,%6,%7}, {%8,%9}, {%0,%1,%2,%3};"
        : "+f"(c[0]), "+f"(c[1]), "+f"(c[2]), "+f"(c[3])
        : "r"(a[0]), "r"(a[1]), "r"(a[2]), "r"(a[3]), "r"(b[0]), "r"(b[1]));
}

__device__ __forceinline__ void mma_bf16(float* c, const uint32_t* a, const uint32_t* b) {
    asm volatile(
        "mma.sync.aligned.m16n8k16.row.col.f32.bf16.bf16.f32 "
        "{%0,%1,%2,%3}, {%4,%5,%6,%7}, {%8,%9}, {%0,%1,%2,%3};"
        : "+f"(c[0]), "+f"(c[1]), "+f"(c[2]), "+f"(c[3])
        : "r"(a[0]), "r"(a[1]), "r"(a[2]), "r"(a[3]), "r"(b[0]), "r"(b[1]));
}

__device__ __forceinline__ uint32_t b2bits(__nv_bfloat162 v) {
    return *reinterpret_cast<uint32_t*>(&v);
}

__device__ __forceinline__ void cp16(void* dst_smem, const void* src) {
    uint32_t d = (uint32_t)__cvta_generic_to_shared(dst_smem);
    asm volatile("cp.async.cg.shared.global [%0], [%1], 16;" :: "r"(d), "l"(src));
}
#define CP_COMMIT() asm volatile("cp.async.commit_group;")
#define CP_WAIT0()  asm volatile("cp.async.wait_group 0;")

// ---------------------------------------------------------------------------
// GEMM (R11/R13 verbatim, proven)
// ---------------------------------------------------------------------------
#define APAD 20
#define WPAD 136

__global__ void __launch_bounds__(256) gemm_xz_kernel(
    const float* __restrict__ Aext, const float* __restrict__ W,
    const float* __restrict__ bias, int layer0)
{
    __shared__ __align__(16) float As[2][128][APAD];
    __shared__ __align__(16) float Ws[2][16][WPAD];

    const int tid = threadIdx.x;
    const int bm = blockIdx.y * 128;
    const int bn = blockIdx.x * 128;

    const int wid = tid >> 5;
    const int lane = tid & 31;
    const int wm = wid >> 2;
    const int wn = wid & 3;
    const int gid = lane >> 2;
    const int tig = lane & 3;

    const int aRow = tid >> 1;
    const int aOff = (tid & 1) << 3;
    const float* aptr;
    {
        const int m = bm + aRow;
        if (layer0) aptr = Aext + ((size_t)(m & 63) * Tt + (m >> 6)) * Dd;
        else        aptr = g_hs0 + (size_t)m * Hh;
    }
    const int wRow = tid >> 4;
    const int wOff = (tid & 15) << 3;
    const float* wptr = W + (size_t)wRow * G4 + bn + wOff;

    cp16(&As[0][aRow][aOff],     aptr + aOff);
    cp16(&As[0][aRow][aOff + 4], aptr + aOff + 4);
    cp16(&Ws[0][wRow][wOff],     wptr);
    cp16(&Ws[0][wRow][wOff + 4], wptr + 4);
    CP_COMMIT();

    float acc[4][4][4];
#pragma unroll
    for (int i = 0; i < 4; i++)
#pragma unroll
        for (int j = 0; j < 4; j++)
#pragma unroll
            for (int q = 0; q < 4; q++) acc[i][j][q] = 0.0f;

    for (int k0 = 0; k0 < 1024; k0 += 16) {
        CP_WAIT0();
        __syncthreads();
        const int buf = (k0 >> 4) & 1;
        if (k0 + 16 < 1024) {
            const int nb = buf ^ 1;
            const float* an = aptr + k0 + 16;
            const float* wn_ = wptr + (size_t)(k0 + 16) * G4;
            cp16(&As[nb][aRow][aOff],     an + aOff);
            cp16(&As[nb][aRow][aOff + 4], an + aOff + 4);
            cp16(&Ws[nb][wRow][wOff],     wn_);
            cp16(&Ws[nb][wRow][wOff + 4], wn_ + 4);
            CP_COMMIT();
        }
#pragma unroll
        for (int s = 0; s < 2; s++) {
            const int ks = s * 8;
            uint32_t a_hi[4][4], a_lo[4][4], b_hi[4][2], b_lo[4][2];
#pragma unroll
            for (int mt = 0; mt < 4; mt++) {
                const int m = wm * 64 + mt * 16 + gid;
                split_tf32(As[buf][m][ks + tig],         a_hi[mt][0], a_lo[mt][0]);
                split_tf32(As[buf][m + 8][ks + tig],     a_hi[mt][1], a_lo[mt][1]);
                split_tf32(As[buf][m][ks + tig + 4],     a_hi[mt][2], a_lo[mt][2]);
                split_tf32(As[buf][m + 8][ks + tig + 4], a_hi[mt][3], a_lo[mt][3]);
            }
#pragma unroll
            for (int nt = 0; nt < 4; nt++) {
                const int n = wn * 32 + nt * 8 + gid;
                split_tf32(Ws[buf][ks + tig][n],     b_hi[nt][0], b_lo[nt][0]);
                split_tf32(Ws[buf][ks + tig + 4][n], b_hi[nt][1], b_lo[nt][1]);
            }
#pragma unroll
            for (int mt = 0; mt < 4; mt++)
#pragma unroll
                for (int nt = 0; nt < 4; nt++) {
                    mma_tf32(acc[mt][nt], a_hi[mt], b_hi[nt]);
                    mma_tf32(acc[mt][nt], a_hi[mt], b_lo[nt]);
                    mma_tf32(acc[mt][nt], a_lo[mt], b_hi[nt]);
                }
        }
    }

#pragma unroll
    for (int mt = 0; mt < 4; mt++) {
#pragma unroll
        for (int nt = 0; nt < 4; nt++) {
            const int gn = bn + wn * 32 + nt * 8 + 2 * tig;
            const float b0v = bias[gn];
            const float b1v = bias[gn + 1];
            const int r0 = bm + wm * 64 + mt * 16 + gid;
            float* p0 = g_xz + (size_t)r0 * G4 + gn;
            float* p1 = g_xz + (size_t)(r0 + 8) * G4 + gn;
            p0[0] = acc[mt][nt][0] + b0v;
            p0[1] = acc[mt][nt][1] + b1v;
            p1[0] = acc[mt][nt][2] + b0v;
            p1[1] = acc[mt][nt][3] + b1v;
        }
    }
}

// ---------------------------------------------------------------------------
// U prep: bf16 hi/lo, m16n8k16 B-frag order (R9 verbatim)
// i = ((((blk*2 + kw)*32 + ks)*4 + nt)*32 + lane)
// ---------------------------------------------------------------------------
__global__ void __launch_bounds__(256) prep_upk_kernel(const float* __restrict__ U) {
    const int i = blockIdx.x * 256 + threadIdx.x;   // 0..1048575
    const int lane = i & 31;
    const int nt   = (i >> 5) & 3;
    const int ks   = (i >> 7) & 31;
    const int kw   = (i >> 12) & 1;
    const int blk  = i >> 13;
    const int tig = lane & 3;
    const int gid = lane >> 2;
    const int kA = kw * 512 + ks * 16 + 2 * tig;
    const int col = nt * Hh + blk * 8 + gid;

    const float u00 = U[(size_t)kA * G4 + col];
    const float u01 = U[(size_t)(kA + 1) * G4 + col];
    const float u10 = U[(size_t)(kA + 8) * G4 + col];
    const float u11 = U[(size_t)(kA + 9) * G4 + col];

    __nv_bfloat162 h0 = __floats2bfloat162_rn(u00, u01);
    __nv_bfloat162 h1 = __floats2bfloat162_rn(u10, u11);
    __nv_bfloat162 l0 = __floats2bfloat162_rn(u00 - __bfloat162float(h0.x),
                                              u01 - __bfloat162float(h0.y));
    __nv_bfloat162 l1 = __floats2bfloat162_rn(u10 - __bfloat162float(h1.x),
                                              u11 - __bfloat162float(h1.y));
    uint4 v;
    v.x = b2bits(h0); v.y = b2bits(h1); v.z = b2bits(l0); v.w = b2bits(l1);
    g_Upk[i] = v;
}

// ---------------------------------------------------------------------------
// Persistent bf16 scan (R9 verbatim) + ATOMIC-POLL barrier (the only change)
// U smem-resident; h streamed as pre-split bf16x2 hi/lo pair-words.
// ---------------------------------------------------------------------------
#define SCAN_SMEM (131072 + 73728 + 8192)   // U + h bufs + reduction = 212992 B

__global__ void __launch_bounds__(256, 1) lstm_scan_tc(
    const int* __restrict__ lengths, float* __restrict__ out_base,
    float* __restrict__ out_tail, int layer)
{
    extern __shared__ uint8_t smraw[];
    uint4* usm = (uint4*)smraw;                          // [kw][ks32][nt4][lane32]
    uint32_t* hsm = (uint32_t*)(smraw + 131072);         // [kw][stage2][hl2][32][72]
    float* red = (float*)(smraw + 131072 + 73728);       // [16][128]

    const int tid = threadIdx.x;
    const int blk = blockIdx.x;
    const int wid = tid >> 5;
    const int lane = tid & 31;
    const int gid = lane >> 2;
    const int tig = lane & 3;
    const int kw = tid >> 7;
    const int gtid = tid & 127;
    const int w4 = wid & 3;
    const int j0 = blk * 8;
    unsigned sense = 0;

    // U resident fill: 64 KB per group (once)
    {
        const uint4* usrc = g_Upk + ((size_t)(blk * 2 + kw)) * 4096 + gtid * 32;
        uint4* udst = usm + kw * 4096 + gtid * 32;
#pragma unroll
        for (int q = 0; q < 32; q++) cp16(udst + q, usrc + q);
    }
    CP_COMMIT();

    // zero initial h (parity 0, hi+lo)
    {
        uint2* p = reinterpret_cast<uint2*>(&g_hP[0][0][0][0]);
        __stcg(p + (blk * 256 + tid), make_uint2(0u, 0u));
    }

    const int b0 = w4 * 16 + gid;
    const int b1 = b0 + 8;
    const int jA = j0 + 2 * tig;
    const int k2g = blk * 4 + tig;
    int len0 = 0, len1 = 0;
    if (kw == 0) { len0 = lengths[b0]; len1 = lengths[b1]; }

    float cb[4] = {0.f, 0.f, 0.f, 0.f};
    float hp[4] = {0.f, 0.f, 0.f, 0.f};

    grid_sync(sense, gridDim.x);   // sync #1

    const int prow = gtid >> 1;
    const int phl = prow >> 5;
    const int pr  = prow & 31;
    const int pcol = (gtid & 1) * 32;
    uint32_t* hgrp = hsm + kw * 9216;

    for (int t = 0; t < Tt; t++) {
        const float* xz = g_xz + (size_t)t * (Bz * G4);
        float2 xv[4][2];
        if (kw == 0) {
#pragma unroll
            for (int g = 0; g < 4; g++) {
                xv[g][0] = *(const float2*)(xz + (size_t)b0 * G4 + g * Hh + jA);
                xv[g][1] = *(const float2*)(xz + (size_t)b1 * G4 + g * Hh + jA);
            }
        }
        if (t) grid_sync(sense, gridDim.x);
        const int par = t & 1;

        float accA[4][4], accB[4][4], accC[4][4];
#pragma unroll
        for (int nt = 0; nt < 4; nt++)
#pragma unroll
            for (int q = 0; q < 4; q++) {
                accA[nt][q] = 0.f; accB[nt][q] = 0.f; accC[nt][q] = 0.f;
            }

        // prefetch chunk 0
        {
            const uint32_t* hsrc = &g_hP[par][phl][kw * 256 + pr][0] + pcol;
            uint32_t* hdst = hgrp + phl * 2304 + pr * 72 + pcol;
#pragma unroll
            for (int q = 0; q < 8; q++) cp16(hdst + q * 4, hsrc + q * 4);
        }
        CP_COMMIT();

        for (int c = 0; c < 8; c++) {
            const int s = c & 1;
            CP_WAIT0();
            __syncthreads();
            if (c < 7) {
                const uint32_t* hsrc = &g_hP[par][phl][kw * 256 + (c + 1) * 32 + pr][0] + pcol;
                uint32_t* hdst = hgrp + (s ^ 1) * 4608 + phl * 2304 + pr * 72 + pcol;
#pragma unroll
                for (int q = 0; q < 8; q++) cp16(hdst + q * 4, hsrc + q * 4);
                CP_COMMIT();
            }
            const uint32_t* Hhi = hgrp + s * 4608;
            const uint32_t* Hlo = Hhi + 2304;
            const uint4* Ug = usm + kw * 4096;
#pragma unroll
            for (int sk = 0; sk < 4; sk++) {
                const int r0 = sk * 8 + tig;
                const int r1 = r0 + 4;
                uint32_t ah[4], al[4];
                ah[0] = Hhi[r0 * 72 + b0]; ah[1] = Hhi[r0 * 72 + b1];
                ah[2] = Hhi[r1 * 72 + b0]; ah[3] = Hhi[r1 * 72 + b1];
                al[0] = Hlo[r0 * 72 + b0]; al[1] = Hlo[r0 * 72 + b1];
                al[2] = Hlo[r1 * 72 + b0]; al[3] = Hlo[r1 * 72 + b1];
                const int ksg = c * 4 + sk;
#pragma unroll
                for (int nt = 0; nt < 4; nt++) {
                    const uint4 v = Ug[(ksg * 4 + nt) * 32 + lane];
                    uint32_t bh[2], bl[2];
                    bh[0] = v.x; bh[1] = v.y; bl[0] = v.z; bl[1] = v.w;
                    mma_bf16(accA[nt], ah, bh);
                    mma_bf16(accB[nt], ah, bl);
                    mma_bf16(accC[nt], al, bh);
                }
            }
        }
        __syncthreads();

        if (kw == 1) {
#pragma unroll
            for (int nt = 0; nt < 4; nt++)
#pragma unroll
                for (int q = 0; q < 4; q++)
                    red[(nt * 4 + q) * 128 + w4 * 32 + lane] =
                        accA[nt][q] + accB[nt][q] + accC[nt][q];
        }
        __syncthreads();

        if (kw == 0) {
            float h2a[4];
#pragma unroll
            for (int q = 0; q < 4; q++) {
                const int r = q >> 1;
                const int ccsel = q & 1;
                const float zi = accA[0][q] + accB[0][q] + accC[0][q]
                               + red[(0 * 4 + q) * 128 + w4 * 32 + lane]
                               + (ccsel ? xv[0][r].y : xv[0][r].x);
                const float zf = accA[1][q] + accB[1][q] + accC[1][q]
                               + red[(1 * 4 + q) * 128 + w4 * 32 + lane]
                               + (ccsel ? xv[1][r].y : xv[1][r].x);
                const float zg = accA[2][q] + accB[2][q] + accC[2][q]
                               + red[(2 * 4 + q) * 128 + w4 * 32 + lane]
                               + (ccsel ? xv[2][r].y : xv[2][r].x);
                const float zo = accA[3][q] + accB[3][q] + accC[3][q]
                               + red[(3 * 4 + q) * 128 + w4 * 32 + lane]
                               + (ccsel ? xv[3][r].y : xv[3][r].x);

                const float ig = 1.0f / (1.0f + __expf(-zi));
                const float fg = 1.0f / (1.0f + __expf(-zf));
                const float gg = tanhf(zg);
                const float og = 1.0f / (1.0f + __expf(-zo));

                const float cn = fg * cb[q] + ig * gg;
                const float hn = og * tanhf(cn);

                const bool msk = t < (r ? len1 : len0);
                const float h2 = msk ? hn : hp[q];
                const float c2 = msk ? cn : cb[q];
                hp[q] = h2; cb[q] = c2;
                h2a[q] = h2;

                const int b = r ? b1 : b0;
                const int j = jA + ccsel;
                if (layer == 0) {
                    g_hs0[(size_t)t * (Bz * Hh) + (size_t)b * Hh + j] = h2;
                } else {
                    out_base[(size_t)b * ((size_t)Tt * Hh) + (size_t)t * Hh + j] = h2;
                }
            }
            {
                __nv_bfloat162 vh = __floats2bfloat162_rn(h2a[0], h2a[1]);
                __nv_bfloat162 vl = __floats2bfloat162_rn(
                    h2a[0] - __bfloat162float(vh.x), h2a[1] - __bfloat162float(vh.y));
                __stcg(&g_hP[par ^ 1][0][k2g][b0], b2bits(vh));
                __stcg(&g_hP[par ^ 1][1][k2g][b0], b2bits(vl));
            }
            {
                __nv_bfloat162 vh = __floats2bfloat162_rn(h2a[2], h2a[3]);
                __nv_bfloat162 vl = __floats2bfloat162_rn(
                    h2a[2] - __bfloat162float(vh.x), h2a[3] - __bfloat162float(vh.y));
                __stcg(&g_hP[par ^ 1][0][k2g][b1], b2bits(vh));
                __stcg(&g_hP[par ^ 1][1][k2g][b1], b2bits(vl));
            }
        }
    }

    if (layer && kw == 0) {
#pragma unroll
        for (int q = 0; q < 4; q++) {
            const int b = (q >> 1) ? b1 : b0;
            const int j = jA + (q & 1);
            out_tail[(size_t)b * Hh + j] = hp[q];
            out_tail[(size_t)Bz * Hh + (size_t)b * Hh + j] = cb[q];
        }
    }
}

extern "C" void kernel_launch(void* const* d_in, const int* in_sizes, int n_in,
                              void* d_out, int out_size) {
    (void)in_sizes; (void)n_in; (void)out_size;
    const float* x  = (const float*)d_in[0];
    const int* lens = (const int*)d_in[1];
    const float* W0 = (const float*)d_in[2];
    const float* U0 = (const float*)d_in[3];
    const float* b0 = (const float*)d_in[4];
    const float* W1 = (const float*)d_in[5];
    const float* U1 = (const float*)d_in[6];
    const float* b1 = (const float*)d_in[7];
    float* out = (float*)d_out;

    cudaFuncSetAttribute(lstm_scan_tc,
                         cudaFuncAttributeMaxDynamicSharedMemorySize, SCAN_SMEM);

    const dim3 ggrid(G4 / 128, (Tt * Bz) / 128);

    gemm_xz_kernel<<<ggrid, 256>>>(x, W0, b0, 1);
    prep_upk_kernel<<<4096, 256>>>(U0);
    lstm_scan_tc<<<128, 256, SCAN_SMEM>>>(lens, nullptr, nullptr, 0);

    gemm_xz_kernel<<<ggrid, 256>>>(nullptr, W1, b1, 0);
    prep_upk_kernel<<<4096, 256>>>(U1);
    float* tail = out + (size_t)Bz * Tt * Hh;
    lstm_scan_tc<<<128, 256, SCAN_SMEM>>>(lens, out, tail, 1);
}